// round 8
// baseline (speedup 1.0000x reference)
#include <cuda_runtime.h>

// GraphVampNet EGNN, sm_103a. Round 8: pair-split (2 lanes/node, 8 outputs),
// 2-edge pairing, two-pointer partner-half GEMVs — now tuned for 4 CTAs/SM
// (single wave of all 512 CTAs): per-layer weight staging (smem ~41KB) and
// <=64 regs (pre[] moved to smem).
// B=512 frames, N=128 nodes, K=16 neighbors (j=(i+d)&127), H=16, NL=4, NC=6.

#define B_  512
#define N_  128
#define K_  16
#define H_  16
#define NC_ 6
#define NL_ 4

#define SZ_E1 (34*16)   // 544
#define SZ_E2 (16*16)
#define SZ_N1 (32*16)
#define SZ_N2 (16*16)
#define SZ_C1 (16*16)
#define SZ_C2 (16)

#define FULL 0xffffffffu
#define HS 20   // node-state row stride (words): 16B-aligned, conflict-spread

__device__ __forceinline__ float silu_f(float v) {
    return __fdividef(v, 1.0f + __expf(-v));   // MUFU; rel err ~1e-6
}
__device__ __forceinline__ float4 ld4(const float* p) {
    return *reinterpret_cast<const float4*>(p);
}
__device__ __forceinline__ void fma8(float (&acc)[8], float s, const float* w) {
    float4 w0 = ld4(w), w1 = ld4(w + 4);
    acc[0] = fmaf(s, w0.x, acc[0]); acc[1] = fmaf(s, w0.y, acc[1]);
    acc[2] = fmaf(s, w0.z, acc[2]); acc[3] = fmaf(s, w0.w, acc[3]);
    acc[4] = fmaf(s, w1.x, acc[4]); acc[5] = fmaf(s, w1.y, acc[5]);
    acc[6] = fmaf(s, w1.z, acc[6]); acc[7] = fmaf(s, w1.w, acc[7]);
}
__device__ __forceinline__ void fma8x2(float (&A)[8], float (&B)[8],
                                       float sa, float sb, const float* w) {
    float4 w0 = ld4(w), w1 = ld4(w + 4);
    A[0] = fmaf(sa, w0.x, A[0]); B[0] = fmaf(sb, w0.x, B[0]);
    A[1] = fmaf(sa, w0.y, A[1]); B[1] = fmaf(sb, w0.y, B[1]);
    A[2] = fmaf(sa, w0.z, A[2]); B[2] = fmaf(sb, w0.z, B[2]);
    A[3] = fmaf(sa, w0.w, A[3]); B[3] = fmaf(sb, w0.w, B[3]);
    A[4] = fmaf(sa, w1.x, A[4]); B[4] = fmaf(sb, w1.x, B[4]);
    A[5] = fmaf(sa, w1.y, A[5]); B[5] = fmaf(sb, w1.y, B[5]);
    A[6] = fmaf(sa, w1.z, A[6]); B[6] = fmaf(sb, w1.z, B[6]);
    A[7] = fmaf(sa, w1.w, A[7]); B[7] = fmaf(sb, w1.w, B[7]);
}
__device__ __forceinline__ void bias8(float (&acc)[8], const float* p) {
    float4 b0 = ld4(p), b1 = ld4(p + 4);
    acc[0] = b0.x; acc[1] = b0.y; acc[2] = b0.z; acc[3] = b0.w;
    acc[4] = b1.x; acc[5] = b1.y; acc[6] = b1.z; acc[7] = b1.w;
}
__device__ __forceinline__ void load16(float (&r)[16], const float* p) {
    float4 v0 = ld4(p), v1 = ld4(p+4), v2 = ld4(p+8), v3 = ld4(p+12);
    r[0]=v0.x; r[1]=v0.y; r[2]=v0.z; r[3]=v0.w;
    r[4]=v1.x; r[5]=v1.y; r[6]=v1.z; r[7]=v1.w;
    r[8]=v2.x; r[9]=v2.y; r[10]=v2.z; r[11]=v2.w;
    r[12]=v3.x; r[13]=v3.y; r[14]=v3.z; r[15]=v3.w;
}
__device__ __forceinline__ void st8(float* p, const float (&a)[8]) {
    *reinterpret_cast<float4*>(p)     = make_float4(a[0], a[1], a[2], a[3]);
    *reinterpret_cast<float4*>(p + 4) = make_float4(a[4], a[5], a[6], a[7]);
}
__device__ __forceinline__ void cpy4(float* dst, const float* src, int n, int tid, int nt) {
    for (int t = tid; t < n / 4; t += nt)
        reinterpret_cast<float4*>(dst)[t] = reinterpret_cast<const float4*>(src)[t];
}

__global__ void __launch_bounds__(2 * N_, 4)
egnn_kernel(const float* __restrict__ data,      // [B, N, 3+N]
            const float* __restrict__ emb_w,     // [N, H]
            const float* __restrict__ ein_w, const float* __restrict__ ein_b,
            const float* __restrict__ eout_w, const float* __restrict__ eout_b,
            const float* __restrict__ fc_w,  const float* __restrict__ fc_b,
            const float* __restrict__ e1_w,  const float* __restrict__ e1_b,
            const float* __restrict__ e2_w,  const float* __restrict__ e2_b,
            const float* __restrict__ n1_w,  const float* __restrict__ n1_b,
            const float* __restrict__ n2_w,  const float* __restrict__ n2_b,
            const float* __restrict__ c1_w,  const float* __restrict__ c1_b,
            const float* __restrict__ c2_w,
            float* __restrict__ out)             // [B, NC]
{
    const int b   = blockIdx.x;
    const int tid = threadIdx.x;
    const int i   = tid >> 1;        // node 0..127
    const int e   = tid & 1;         // lane within pair
    const int co  = e * 8;           // owned output-column slice base

    // node state
    __shared__ __align__(16) float s_h[N_][HS];     // pair-private features
    __shared__ __align__(16) float s_y[N_][HS];     // e1 neighbor-half
    __shared__ __align__(16) float s_pre[N_][HS];   // e1 self-half (pre)
    __shared__ __align__(16) float4 s_x4[N_];       // coords
    __shared__ float s_pool[H_];

    // current-layer weights (staged from L2 each layer)
    __shared__ __align__(16) float wb_e1[SZ_E1], wb_e2[SZ_E2];
    __shared__ __align__(16) float wb_n1[SZ_N1], wb_n2[SZ_N2];
    __shared__ __align__(16) float wb_c1[SZ_C1], wb_c2[SZ_C2];
    __shared__ __align__(16) float be1[16], be2[16], bn1[16], bn2[16], bc1[16];

    const int NT = 2 * N_;

    float xi0, xi1, xi2;
    {
        const float* dptr = data + ((size_t)b * N_ + i) * (3 + N_);
        xi0 = dptr[0]; xi1 = dptr[1]; xi2 = dptr[2];
    }

    // ---- init: h = emb @ ein_w + ein_b  (weights direct from global/L2) ----
    {
        float acc[8];
        bias8(acc, ein_b + co);
        const float* er = emb_w + i * H_;
        #pragma unroll
        for (int k = 0; k < 16; ++k) fma8(acc, er[k], ein_w + k * 16 + co);
        st8(&s_h[i][co], acc);
        if (e == 0) s_x4[i] = make_float4(xi0, xi1, xi2, 0.0f);
    }

    // ---- E_GCL layers ----
    #pragma unroll 1
    for (int l = 0; l < NL_; ++l) {
        __syncthreads();   // prior layer's readers done; init/s_x4 visible
        // stage this layer's weights (contiguous slices, hot in L2)
        cpy4(wb_e1, e1_w + l * SZ_E1, SZ_E1, tid, NT);
        cpy4(wb_e2, e2_w + l * SZ_E2, SZ_E2, tid, NT);
        cpy4(wb_n1, n1_w + l * SZ_N1, SZ_N1, tid, NT);
        cpy4(wb_n2, n2_w + l * SZ_N2, SZ_N2, tid, NT);
        cpy4(wb_c1, c1_w + l * SZ_C1, SZ_C1, tid, NT);
        if (tid < 16) {
            wb_c2[tid] = c2_w[l * 16 + tid];
            be1[tid] = e1_b[l * 16 + tid];
            be2[tid] = e2_b[l * 16 + tid];
            bn1[tid] = n1_b[l * 16 + tid];
            bn2[tid] = n2_b[l * 16 + tid];
            bc1[tid] = c1_b[l * 16 + tid];
        }
        __syncthreads();

        const float* We1c = wb_e1 + co;
        const float* E2o = wb_e2 + co * 16       + co;
        const float* E2x = wb_e2 + (8 - co) * 16 + co;
        const float* C1o = wb_c1 + co * 16       + co;
        const float* C1x = wb_c1 + (8 - co) * 16 + co;

        // Phase A (per node): pre = bias + e_attr row + h_i @ rows0-15 -> s_pre;
        //                     y_i = h_i @ rows16-31 -> s_y   (own 8 cols each)
        {
            float hf[16]; load16(hf, &s_h[i][0]);
            float pq[8], yq[8];
            bias8(pq, be1 + co);
            fma8(pq, 1.0f, We1c + 33 * 16);
            #pragma unroll
            for (int o = 0; o < 8; ++o) yq[o] = 0.0f;
            #pragma unroll
            for (int k = 0; k < 16; ++k) {
                fma8(pq, hf[k], We1c + k * 16);
                fma8(yq, hf[k], We1c + (16 + k) * 16);
            }
            st8(&s_pre[i][co], pq);
            st8(&s_y[i][co], yq);
        }
        __syncthreads();   // s_pre / s_y visible

        float accm[8] = {0,0,0,0,0,0,0,0};
        float ax0 = 0.f, ax1 = 0.f, ax2 = 0.f;

        #pragma unroll 1
        for (int it = 0; it < 8; ++it) {
            const int d  = 1 + 2 * it;
            const int j0 = (i + d)     & (N_ - 1);
            const int j1 = (i + d + 1) & (N_ - 1);
            float4 xj0 = s_x4[j0];
            float4 xj1 = s_x4[j1];
            const float d00 = xi0-xj0.x, d01 = xi1-xj0.y, d02 = xi2-xj0.z;
            const float d10 = xi0-xj1.x, d11 = xi1-xj1.y, d12 = xi2-xj1.z;
            const float rad0 = fmaf(d00,d00, fmaf(d01,d01, d02*d02));
            const float rad1 = fmaf(d10,d10, fmaf(d11,d11, d12*d12));

            // e1: a = silu(pre + y_j + rad * w_row32)   (own 8 cols)
            float a0[8], a1[8];
            {
                float4 pa = ld4(&s_pre[i][co]), pb = ld4(&s_pre[i][co+4]);
                float4 w0 = ld4(We1c + 32*16),  w1 = ld4(We1c + 32*16 + 4);
                float4 ya = ld4(&s_y[j0][co]),  yb = ld4(&s_y[j0][co+4]);
                float4 za = ld4(&s_y[j1][co]),  zb = ld4(&s_y[j1][co+4]);
                a0[0]=silu_f(fmaf(rad0,w0.x, pa.x+ya.x));
                a0[1]=silu_f(fmaf(rad0,w0.y, pa.y+ya.y));
                a0[2]=silu_f(fmaf(rad0,w0.z, pa.z+ya.z));
                a0[3]=silu_f(fmaf(rad0,w0.w, pa.w+ya.w));
                a0[4]=silu_f(fmaf(rad0,w1.x, pb.x+yb.x));
                a0[5]=silu_f(fmaf(rad0,w1.y, pb.y+yb.y));
                a0[6]=silu_f(fmaf(rad0,w1.z, pb.z+yb.z));
                a0[7]=silu_f(fmaf(rad0,w1.w, pb.w+yb.w));
                a1[0]=silu_f(fmaf(rad1,w0.x, pa.x+za.x));
                a1[1]=silu_f(fmaf(rad1,w0.y, pa.y+za.y));
                a1[2]=silu_f(fmaf(rad1,w0.z, pa.z+za.z));
                a1[3]=silu_f(fmaf(rad1,w0.w, pa.w+za.w));
                a1[4]=silu_f(fmaf(rad1,w1.x, pb.x+zb.x));
                a1[5]=silu_f(fmaf(rad1,w1.y, pb.y+zb.y));
                a1[6]=silu_f(fmaf(rad1,w1.z, pb.z+zb.z));
                a1[7]=silu_f(fmaf(rad1,w1.w, pb.w+zb.w));
            }

            // e2: m = silu(a_full @ We2 + b); partner half via shfl_xor + offset base
            float m0[8], m1[8];
            bias8(m0, be2 + co);
            #pragma unroll
            for (int o = 0; o < 8; ++o) m1[o] = m0[o];
            #pragma unroll
            for (int r = 0; r < 8; ++r) fma8x2(m0, m1, a0[r], a1[r], E2o + r * 16);
            #pragma unroll
            for (int r = 0; r < 8; ++r) {
                const float s0 = __shfl_xor_sync(FULL, a0[r], 1);
                const float s1 = __shfl_xor_sync(FULL, a1[r], 1);
                fma8x2(m0, m1, s0, s1, E2x + r * 16);
            }
            #pragma unroll
            for (int o = 0; o < 8; ++o) {
                m0[o] = silu_f(m0[o]); m1[o] = silu_f(m1[o]);
                accm[o] += m0[o] + m1[o];
            }

            // coord_mlp: t = silu(m_full @ Wc1 + b) . Wc2 (reuse a as accum)
            bias8(a0, bc1 + co);
            #pragma unroll
            for (int o = 0; o < 8; ++o) a1[o] = a0[o];
            #pragma unroll
            for (int r = 0; r < 8; ++r) fma8x2(a0, a1, m0[r], m1[r], C1o + r * 16);
            #pragma unroll
            for (int r = 0; r < 8; ++r) {
                const float s0 = __shfl_xor_sync(FULL, m0[r], 1);
                const float s1 = __shfl_xor_sync(FULL, m1[r], 1);
                fma8x2(a0, a1, s0, s1, C1x + r * 16);
            }
            float t0, t1;
            {
                float4 w0 = ld4(wb_c2 + co), w1 = ld4(wb_c2 + co + 4);
                t0 = silu_f(a0[0]) * w0.x;
                t0 = fmaf(silu_f(a0[1]), w0.y, t0);
                t0 = fmaf(silu_f(a0[2]), w0.z, t0);
                t0 = fmaf(silu_f(a0[3]), w0.w, t0);
                t0 = fmaf(silu_f(a0[4]), w1.x, t0);
                t0 = fmaf(silu_f(a0[5]), w1.y, t0);
                t0 = fmaf(silu_f(a0[6]), w1.z, t0);
                t0 = fmaf(silu_f(a0[7]), w1.w, t0);
                t1 = silu_f(a1[0]) * w0.x;
                t1 = fmaf(silu_f(a1[1]), w0.y, t1);
                t1 = fmaf(silu_f(a1[2]), w0.z, t1);
                t1 = fmaf(silu_f(a1[3]), w0.w, t1);
                t1 = fmaf(silu_f(a1[4]), w1.x, t1);
                t1 = fmaf(silu_f(a1[5]), w1.y, t1);
                t1 = fmaf(silu_f(a1[6]), w1.z, t1);
                t1 = fmaf(silu_f(a1[7]), w1.w, t1);
            }
            t0 += __shfl_xor_sync(FULL, t0, 1);
            t1 += __shfl_xor_sync(FULL, t1, 1);

            ax0 = fmaf(d00, t0, fmaf(d10, t1, ax0));
            ax1 = fmaf(d01, t0, fmaf(d11, t1, ax1));
            ax2 = fmaf(d02, t0, fmaf(d12, t1, ax2));
        }

        xi0 = fmaf(ax0, 0.0625f, xi0);   // cnt == 16
        xi1 = fmaf(ax1, 0.0625f, xi1);
        xi2 = fmaf(ax2, 0.0625f, xi2);

        // Phase C: node_mlp (pair-split 8/8); accm/na exchanged via shfl_xor
        {
            const float* Wn1c = wb_n1 + co;
            const float* N1o = wb_n1 + (16 + co) * 16     + co;
            const float* N1x = wb_n1 + (16 + 8 - co) * 16 + co;
            const float* N2o = wb_n2 + co * 16       + co;
            const float* N2x = wb_n2 + (8 - co) * 16 + co;

            float hf[16]; load16(hf, &s_h[i][0]);   // old h (pair-private)
            float na[8];
            bias8(na, bn1 + co);
            #pragma unroll
            for (int k = 0; k < 16; ++k) fma8(na, hf[k], Wn1c + k * 16);
            #pragma unroll
            for (int r = 0; r < 8; ++r) fma8(na, accm[r], N1o + r * 16);
            #pragma unroll
            for (int r = 0; r < 8; ++r)
                fma8(na, __shfl_xor_sync(FULL, accm[r], 1), N1x + r * 16);
            #pragma unroll
            for (int o = 0; o < 8; ++o) na[o] = silu_f(na[o]);

            float hb[8];
            bias8(hb, bn2 + co);
            #pragma unroll
            for (int r = 0; r < 8; ++r) fma8(hb, na[r], N2o + r * 16);
            #pragma unroll
            for (int r = 0; r < 8; ++r)
                fma8(hb, __shfl_xor_sync(FULL, na[r], 1), N2x + r * 16);
            {   // residual from own smem slice (avoids runtime-indexed regs)
                float4 r0 = ld4(&s_h[i][co]), r1 = ld4(&s_h[i][co + 4]);
                hb[0] += r0.x; hb[1] += r0.y; hb[2] += r0.z; hb[3] += r0.w;
                hb[4] += r1.x; hb[5] += r1.y; hb[6] += r1.z; hb[7] += r1.w;
            }
            __syncwarp();          // partner's reads of old s_h row complete
            st8(&s_h[i][co], hb);
            if (e == 0) s_x4[i] = make_float4(xi0, xi1, xi2, 0.0f);
        }
    }
    __syncthreads();

    // ---- embedding_out (weights direct from global/L2) + pooling ----
    {
        float hf[16]; load16(hf, &s_h[i][0]);
        float ho[8];
        bias8(ho, eout_b + co);
        #pragma unroll
        for (int k = 0; k < 16; ++k) fma8(ho, hf[k], eout_w + k * 16 + co);
        st8(&s_h[i][co], ho);   // pair-private overwrite (warp-synchronous)
    }
    __syncthreads();

    if (tid < H_) {
        float s = 0.0f;
        for (int j = 0; j < N_; ++j) s += s_h[j][tid];
        s_pool[tid] = s * (1.0f / (float)N_);
    }
    __syncthreads();

    if (tid == 0) {
        float logit[NC_];
        float mx = -1e30f;
        #pragma unroll
        for (int c = 0; c < NC_; ++c) {
            float s = fc_b[c];
            #pragma unroll
            for (int k = 0; k < H_; ++k) s = fmaf(s_pool[k], fc_w[k * NC_ + c], s);
            logit[c] = s;
            mx = fmaxf(mx, s);
        }
        float den = 0.0f;
        float ev[NC_];
        #pragma unroll
        for (int c = 0; c < NC_; ++c) { ev[c] = expf(logit[c] - mx); den += ev[c]; }
        const float inv = 1.0f / den;
        #pragma unroll
        for (int c = 0; c < NC_; ++c) out[b * NC_ + c] = ev[c] * inv;
    }
}

extern "C" void kernel_launch(void* const* d_in, const int* in_sizes, int n_in,
                              void* d_out, int out_size)
{
    const float* data   = (const float*)d_in[0];
    const float* emb_w  = (const float*)d_in[3];
    const float* ein_w  = (const float*)d_in[4];
    const float* ein_b  = (const float*)d_in[5];
    const float* eout_w = (const float*)d_in[6];
    const float* eout_b = (const float*)d_in[7];
    const float* fc_w   = (const float*)d_in[8];
    const float* fc_b   = (const float*)d_in[9];
    const float* e1_w   = (const float*)d_in[10];
    const float* e1_b   = (const float*)d_in[11];
    const float* e2_w   = (const float*)d_in[12];
    const float* e2_b   = (const float*)d_in[13];
    const float* n1_w   = (const float*)d_in[14];
    const float* n1_b   = (const float*)d_in[15];
    const float* n2_w   = (const float*)d_in[16];
    const float* n2_b   = (const float*)d_in[17];
    const float* c1_w   = (const float*)d_in[18];
    const float* c1_b   = (const float*)d_in[19];
    const float* c2_w   = (const float*)d_in[20];
    float* out = (float*)d_out;

    egnn_kernel<<<B_, 2 * N_>>>(data, emb_w, ein_w, ein_b, eout_w, eout_b,
                                fc_w, fc_b, e1_w, e1_b, e2_w, e2_b,
                                n1_w, n1_b, n2_w, n2_b, c1_w, c1_b, c2_w, out);
}

// round 9
// speedup vs baseline: 1.0536x; 1.0536x over previous
#include <cuda_runtime.h>

// GraphVampNet EGNN, sm_103a. Round 9: pair-split, 2-edge pairing, two-pointer
// partner GEMVs, per-layer weight staging, 4 CTAs/SM single wave.
// Register diet vs R8: pre[] in regs, accm[] in smem, coord-diffs recomputed.
// B=512 frames, N=128 nodes, K=16 neighbors (j=(i+d)&127), H=16, NL=4, NC=6.

#define B_  512
#define N_  128
#define K_  16
#define H_  16
#define NC_ 6
#define NL_ 4

#define SZ_E1 (34*16)   // 544
#define SZ_E2 (16*16)
#define SZ_N1 (32*16)
#define SZ_N2 (16*16)
#define SZ_C1 (16*16)
#define SZ_C2 (16)

#define FULL 0xffffffffu
#define HS 20   // node-state row stride (words): 16B-aligned

__device__ __forceinline__ float silu_f(float v) {
    return __fdividef(v, 1.0f + __expf(-v));   // MUFU; rel err ~1e-6
}
__device__ __forceinline__ float4 ld4(const float* p) {
    return *reinterpret_cast<const float4*>(p);
}
__device__ __forceinline__ void fma8(float (&acc)[8], float s, const float* w) {
    float4 w0 = ld4(w), w1 = ld4(w + 4);
    acc[0] = fmaf(s, w0.x, acc[0]); acc[1] = fmaf(s, w0.y, acc[1]);
    acc[2] = fmaf(s, w0.z, acc[2]); acc[3] = fmaf(s, w0.w, acc[3]);
    acc[4] = fmaf(s, w1.x, acc[4]); acc[5] = fmaf(s, w1.y, acc[5]);
    acc[6] = fmaf(s, w1.z, acc[6]); acc[7] = fmaf(s, w1.w, acc[7]);
}
__device__ __forceinline__ void fma8x2(float (&A)[8], float (&B)[8],
                                       float sa, float sb, const float* w) {
    float4 w0 = ld4(w), w1 = ld4(w + 4);
    A[0] = fmaf(sa, w0.x, A[0]); B[0] = fmaf(sb, w0.x, B[0]);
    A[1] = fmaf(sa, w0.y, A[1]); B[1] = fmaf(sb, w0.y, B[1]);
    A[2] = fmaf(sa, w0.z, A[2]); B[2] = fmaf(sb, w0.z, B[2]);
    A[3] = fmaf(sa, w0.w, A[3]); B[3] = fmaf(sb, w0.w, B[3]);
    A[4] = fmaf(sa, w1.x, A[4]); B[4] = fmaf(sb, w1.x, B[4]);
    A[5] = fmaf(sa, w1.y, A[5]); B[5] = fmaf(sb, w1.y, B[5]);
    A[6] = fmaf(sa, w1.z, A[6]); B[6] = fmaf(sb, w1.z, B[6]);
    A[7] = fmaf(sa, w1.w, A[7]); B[7] = fmaf(sb, w1.w, B[7]);
}
__device__ __forceinline__ void bias8(float (&acc)[8], const float* p) {
    float4 b0 = ld4(p), b1 = ld4(p + 4);
    acc[0] = b0.x; acc[1] = b0.y; acc[2] = b0.z; acc[3] = b0.w;
    acc[4] = b1.x; acc[5] = b1.y; acc[6] = b1.z; acc[7] = b1.w;
}
__device__ __forceinline__ void load16(float (&r)[16], const float* p) {
    float4 v0 = ld4(p), v1 = ld4(p+4), v2 = ld4(p+8), v3 = ld4(p+12);
    r[0]=v0.x; r[1]=v0.y; r[2]=v0.z; r[3]=v0.w;
    r[4]=v1.x; r[5]=v1.y; r[6]=v1.z; r[7]=v1.w;
    r[8]=v2.x; r[9]=v2.y; r[10]=v2.z; r[11]=v2.w;
    r[12]=v3.x; r[13]=v3.y; r[14]=v3.z; r[15]=v3.w;
}
__device__ __forceinline__ void st8(float* p, const float (&a)[8]) {
    *reinterpret_cast<float4*>(p)     = make_float4(a[0], a[1], a[2], a[3]);
    *reinterpret_cast<float4*>(p + 4) = make_float4(a[4], a[5], a[6], a[7]);
}
__device__ __forceinline__ void cpy4(float* dst, const float* src, int n, int tid, int nt) {
    for (int t = tid; t < n / 4; t += nt)
        reinterpret_cast<float4*>(dst)[t] = reinterpret_cast<const float4*>(src)[t];
}

__global__ void __launch_bounds__(2 * N_, 4)
egnn_kernel(const float* __restrict__ data,      // [B, N, 3+N]
            const float* __restrict__ emb_w,     // [N, H]
            const float* __restrict__ ein_w, const float* __restrict__ ein_b,
            const float* __restrict__ eout_w, const float* __restrict__ eout_b,
            const float* __restrict__ fc_w,  const float* __restrict__ fc_b,
            const float* __restrict__ e1_w,  const float* __restrict__ e1_b,
            const float* __restrict__ e2_w,  const float* __restrict__ e2_b,
            const float* __restrict__ n1_w,  const float* __restrict__ n1_b,
            const float* __restrict__ n2_w,  const float* __restrict__ n2_b,
            const float* __restrict__ c1_w,  const float* __restrict__ c1_b,
            const float* __restrict__ c2_w,
            float* __restrict__ out)             // [B, NC]
{
    const int b   = blockIdx.x;
    const int tid = threadIdx.x;
    const int i   = tid >> 1;        // node 0..127
    const int e   = tid & 1;         // lane within pair
    const int co  = e * 8;           // owned output-column slice base

    // node state
    __shared__ __align__(16) float s_h[N_][HS];     // pair-private features
    __shared__ __align__(16) float s_y[N_][HS];     // e1 neighbor-half
    __shared__ __align__(16) float s_acc[N_][HS];   // message accumulator
    __shared__ __align__(16) float4 s_x4[N_];       // coords
    __shared__ float s_pool[H_];

    // current-layer weights (staged from L2 each layer)
    __shared__ __align__(16) float wb_e1[SZ_E1], wb_e2[SZ_E2];
    __shared__ __align__(16) float wb_n1[SZ_N1], wb_n2[SZ_N2];
    __shared__ __align__(16) float wb_c1[SZ_C1], wb_c2[SZ_C2];
    __shared__ __align__(16) float be1[16], be2[16], bn1[16], bn2[16], bc1[16];

    const int NT = 2 * N_;

    float xi0, xi1, xi2;
    {
        const float* dptr = data + ((size_t)b * N_ + i) * (3 + N_);
        xi0 = dptr[0]; xi1 = dptr[1]; xi2 = dptr[2];
    }

    // ---- init: h = emb @ ein_w + ein_b  (weights direct from global/L2) ----
    {
        float acc[8];
        bias8(acc, ein_b + co);
        const float* er = emb_w + i * H_;
        #pragma unroll
        for (int k = 0; k < 16; ++k) fma8(acc, er[k], ein_w + k * 16 + co);
        st8(&s_h[i][co], acc);
        if (e == 0) s_x4[i] = make_float4(xi0, xi1, xi2, 0.0f);
    }

    // ---- E_GCL layers ----
    #pragma unroll 1
    for (int l = 0; l < NL_; ++l) {
        __syncthreads();   // prior layer's readers done; s_x4/s_h visible
        cpy4(wb_e1, e1_w + l * SZ_E1, SZ_E1, tid, NT);
        cpy4(wb_e2, e2_w + l * SZ_E2, SZ_E2, tid, NT);
        cpy4(wb_n1, n1_w + l * SZ_N1, SZ_N1, tid, NT);
        cpy4(wb_n2, n2_w + l * SZ_N2, SZ_N2, tid, NT);
        cpy4(wb_c1, c1_w + l * SZ_C1, SZ_C1, tid, NT);
        if (tid < 16) {
            wb_c2[tid] = c2_w[l * 16 + tid];
            be1[tid] = e1_b[l * 16 + tid];
            be2[tid] = e2_b[l * 16 + tid];
            bn1[tid] = n1_b[l * 16 + tid];
            bn2[tid] = n2_b[l * 16 + tid];
            bc1[tid] = c1_b[l * 16 + tid];
        }
        __syncthreads();

        const float* We1c = wb_e1 + co;
        const float* E2o = wb_e2 + co * 16       + co;
        const float* E2x = wb_e2 + (8 - co) * 16 + co;
        const float* C1o = wb_c1 + co * 16       + co;
        const float* C1x = wb_c1 + (8 - co) * 16 + co;

        // Phase A (per node): pre (regs) = bias + e_attr row + h_i @ rows0-15;
        //                     y_i = h_i @ rows16-31 -> s_y; zero s_acc slice
        float pre[8];
        {
            float hf[16]; load16(hf, &s_h[i][0]);
            bias8(pre, be1 + co);
            fma8(pre, 1.0f, We1c + 33 * 16);
            float yq[8] = {0,0,0,0,0,0,0,0};
            #pragma unroll
            for (int k = 0; k < 16; ++k) {
                fma8(pre, hf[k], We1c + k * 16);
                fma8(yq, hf[k], We1c + (16 + k) * 16);
            }
            st8(&s_y[i][co], yq);
            const float z[8] = {0,0,0,0,0,0,0,0};
            st8(&s_acc[i][co], z);
        }
        __syncthreads();   // s_y visible

        float ax0 = 0.f, ax1 = 0.f, ax2 = 0.f;

        #pragma unroll 1
        for (int it = 0; it < 8; ++it) {
            const int d  = 1 + 2 * it;
            const int j0 = (i + d)     & (N_ - 1);
            const int j1 = (i + d + 1) & (N_ - 1);

            // e1: a = silu(pre + y_j + rad * w_row32)   (own 8 cols)
            float a0[8], a1[8];
            {
                float4 xj0 = s_x4[j0];
                float4 xj1 = s_x4[j1];
                const float d00 = xi0-xj0.x, d01 = xi1-xj0.y, d02 = xi2-xj0.z;
                const float d10 = xi0-xj1.x, d11 = xi1-xj1.y, d12 = xi2-xj1.z;
                const float rad0 = fmaf(d00,d00, fmaf(d01,d01, d02*d02));
                const float rad1 = fmaf(d10,d10, fmaf(d11,d11, d12*d12));
                float4 w0 = ld4(We1c + 32*16), w1 = ld4(We1c + 32*16 + 4);
                float4 ya = ld4(&s_y[j0][co]), yb = ld4(&s_y[j0][co+4]);
                float4 za = ld4(&s_y[j1][co]), zb = ld4(&s_y[j1][co+4]);
                a0[0]=silu_f(fmaf(rad0,w0.x, pre[0]+ya.x));
                a0[1]=silu_f(fmaf(rad0,w0.y, pre[1]+ya.y));
                a0[2]=silu_f(fmaf(rad0,w0.z, pre[2]+ya.z));
                a0[3]=silu_f(fmaf(rad0,w0.w, pre[3]+ya.w));
                a0[4]=silu_f(fmaf(rad0,w1.x, pre[4]+yb.x));
                a0[5]=silu_f(fmaf(rad0,w1.y, pre[5]+yb.y));
                a0[6]=silu_f(fmaf(rad0,w1.z, pre[6]+yb.z));
                a0[7]=silu_f(fmaf(rad0,w1.w, pre[7]+yb.w));
                a1[0]=silu_f(fmaf(rad1,w0.x, pre[0]+za.x));
                a1[1]=silu_f(fmaf(rad1,w0.y, pre[1]+za.y));
                a1[2]=silu_f(fmaf(rad1,w0.z, pre[2]+za.z));
                a1[3]=silu_f(fmaf(rad1,w0.w, pre[3]+za.w));
                a1[4]=silu_f(fmaf(rad1,w1.x, pre[4]+zb.x));
                a1[5]=silu_f(fmaf(rad1,w1.y, pre[5]+zb.y));
                a1[6]=silu_f(fmaf(rad1,w1.z, pre[6]+zb.z));
                a1[7]=silu_f(fmaf(rad1,w1.w, pre[7]+zb.w));
            }

            // e2: m = silu(a_full @ We2 + b); partner half via shfl_xor
            float m0[8], m1[8];
            bias8(m0, be2 + co);
            #pragma unroll
            for (int o = 0; o < 8; ++o) m1[o] = m0[o];
            #pragma unroll
            for (int r = 0; r < 8; ++r) fma8x2(m0, m1, a0[r], a1[r], E2o + r * 16);
            #pragma unroll
            for (int r = 0; r < 8; ++r) {
                const float s0 = __shfl_xor_sync(FULL, a0[r], 1);
                const float s1 = __shfl_xor_sync(FULL, a1[r], 1);
                fma8x2(m0, m1, s0, s1, E2x + r * 16);
            }
            #pragma unroll
            for (int o = 0; o < 8; ++o) { m0[o] = silu_f(m0[o]); m1[o] = silu_f(m1[o]); }

            // accumulate messages in smem (own slice; frees 8 regs)
            {
                float4 p0 = ld4(&s_acc[i][co]), p1 = ld4(&s_acc[i][co+4]);
                p0.x += m0[0] + m1[0]; p0.y += m0[1] + m1[1];
                p0.z += m0[2] + m1[2]; p0.w += m0[3] + m1[3];
                p1.x += m0[4] + m1[4]; p1.y += m0[5] + m1[5];
                p1.z += m0[6] + m1[6]; p1.w += m0[7] + m1[7];
                *reinterpret_cast<float4*>(&s_acc[i][co])   = p0;
                *reinterpret_cast<float4*>(&s_acc[i][co+4]) = p1;
            }

            // coord_mlp: t = silu(m_full @ Wc1 + b) . Wc2 (reuse a as accum)
            bias8(a0, bc1 + co);
            #pragma unroll
            for (int o = 0; o < 8; ++o) a1[o] = a0[o];
            #pragma unroll
            for (int r = 0; r < 8; ++r) fma8x2(a0, a1, m0[r], m1[r], C1o + r * 16);
            #pragma unroll
            for (int r = 0; r < 8; ++r) {
                const float s0 = __shfl_xor_sync(FULL, m0[r], 1);
                const float s1 = __shfl_xor_sync(FULL, m1[r], 1);
                fma8x2(a0, a1, s0, s1, C1x + r * 16);
            }
            float t0, t1;
            {
                float4 w0 = ld4(wb_c2 + co), w1 = ld4(wb_c2 + co + 4);
                t0 = silu_f(a0[0]) * w0.x;
                t0 = fmaf(silu_f(a0[1]), w0.y, t0);
                t0 = fmaf(silu_f(a0[2]), w0.z, t0);
                t0 = fmaf(silu_f(a0[3]), w0.w, t0);
                t0 = fmaf(silu_f(a0[4]), w1.x, t0);
                t0 = fmaf(silu_f(a0[5]), w1.y, t0);
                t0 = fmaf(silu_f(a0[6]), w1.z, t0);
                t0 = fmaf(silu_f(a0[7]), w1.w, t0);
                t1 = silu_f(a1[0]) * w0.x;
                t1 = fmaf(silu_f(a1[1]), w0.y, t1);
                t1 = fmaf(silu_f(a1[2]), w0.z, t1);
                t1 = fmaf(silu_f(a1[3]), w0.w, t1);
                t1 = fmaf(silu_f(a1[4]), w1.x, t1);
                t1 = fmaf(silu_f(a1[5]), w1.y, t1);
                t1 = fmaf(silu_f(a1[6]), w1.z, t1);
                t1 = fmaf(silu_f(a1[7]), w1.w, t1);
            }
            t0 += __shfl_xor_sync(FULL, t0, 1);
            t1 += __shfl_xor_sync(FULL, t1, 1);

            // apply coord contributions (recompute diffs; s_x4 stable in layer)
            {
                float4 xj0 = s_x4[j0];
                float4 xj1 = s_x4[j1];
                ax0 = fmaf(xi0 - xj0.x, t0, fmaf(xi0 - xj1.x, t1, ax0));
                ax1 = fmaf(xi1 - xj0.y, t0, fmaf(xi1 - xj1.y, t1, ax1));
                ax2 = fmaf(xi2 - xj0.z, t0, fmaf(xi2 - xj1.z, t1, ax2));
            }
        }

        xi0 = fmaf(ax0, 0.0625f, xi0);   // cnt == 16
        xi1 = fmaf(ax1, 0.0625f, xi1);
        xi2 = fmaf(ax2, 0.0625f, xi2);

        // Phase C: node_mlp (pair-split 8/8); accm read full-width from smem
        {
            const float* Wn1c = wb_n1 + co;
            const float* N2o = wb_n2 + co * 16       + co;
            const float* N2x = wb_n2 + (8 - co) * 16 + co;

            __syncwarp();   // partner's s_acc slice complete
            float hf[16]; load16(hf, &s_h[i][0]);    // old h (pair-private)
            float af[16]; load16(af, &s_acc[i][0]);  // full agg_m

            float na[8];
            bias8(na, bn1 + co);
            #pragma unroll
            for (int k = 0; k < 16; ++k) {
                fma8(na, hf[k], Wn1c + k * 16);
                fma8(na, af[k], Wn1c + (16 + k) * 16);
            }
            #pragma unroll
            for (int o = 0; o < 8; ++o) na[o] = silu_f(na[o]);

            float hb[8];
            bias8(hb, bn2 + co);
            #pragma unroll
            for (int r = 0; r < 8; ++r) fma8(hb, na[r], N2o + r * 16);
            #pragma unroll
            for (int r = 0; r < 8; ++r)
                fma8(hb, __shfl_xor_sync(FULL, na[r], 1), N2x + r * 16);
            {   // residual from own smem slice
                float4 r0 = ld4(&s_h[i][co]), r1 = ld4(&s_h[i][co + 4]);
                hb[0] += r0.x; hb[1] += r0.y; hb[2] += r0.z; hb[3] += r0.w;
                hb[4] += r1.x; hb[5] += r1.y; hb[6] += r1.z; hb[7] += r1.w;
            }
            __syncwarp();          // partner's reads of old s_h row complete
            st8(&s_h[i][co], hb);
            if (e == 0) s_x4[i] = make_float4(xi0, xi1, xi2, 0.0f);
        }
    }
    __syncthreads();

    // ---- embedding_out (weights direct from global/L2) + pooling ----
    {
        float hf[16]; load16(hf, &s_h[i][0]);
        float ho[8];
        bias8(ho, eout_b + co);
        #pragma unroll
        for (int k = 0; k < 16; ++k) fma8(ho, hf[k], eout_w + k * 16 + co);
        st8(&s_h[i][co], ho);   // pair-private overwrite (warp-synchronous)
    }
    __syncthreads();

    if (tid < H_) {
        float s = 0.0f;
        for (int j = 0; j < N_; ++j) s += s_h[j][tid];
        s_pool[tid] = s * (1.0f / (float)N_);
    }
    __syncthreads();

    if (tid == 0) {
        float logit[NC_];
        float mx = -1e30f;
        #pragma unroll
        for (int c = 0; c < NC_; ++c) {
            float s = fc_b[c];
            #pragma unroll
            for (int k = 0; k < H_; ++k) s = fmaf(s_pool[k], fc_w[k * NC_ + c], s);
            logit[c] = s;
            mx = fmaxf(mx, s);
        }
        float den = 0.0f;
        float ev[NC_];
        #pragma unroll
        for (int c = 0; c < NC_; ++c) { ev[c] = expf(logit[c] - mx); den += ev[c]; }
        const float inv = 1.0f / den;
        #pragma unroll
        for (int c = 0; c < NC_; ++c) out[b * NC_ + c] = ev[c] * inv;
    }
}

extern "C" void kernel_launch(void* const* d_in, const int* in_sizes, int n_in,
                              void* d_out, int out_size)
{
    const float* data   = (const float*)d_in[0];
    const float* emb_w  = (const float*)d_in[3];
    const float* ein_w  = (const float*)d_in[4];
    const float* ein_b  = (const float*)d_in[5];
    const float* eout_w = (const float*)d_in[6];
    const float* eout_b = (const float*)d_in[7];
    const float* fc_w   = (const float*)d_in[8];
    const float* fc_b   = (const float*)d_in[9];
    const float* e1_w   = (const float*)d_in[10];
    const float* e1_b   = (const float*)d_in[11];
    const float* e2_w   = (const float*)d_in[12];
    const float* e2_b   = (const float*)d_in[13];
    const float* n1_w   = (const float*)d_in[14];
    const float* n1_b   = (const float*)d_in[15];
    const float* n2_w   = (const float*)d_in[16];
    const float* n2_b   = (const float*)d_in[17];
    const float* c1_w   = (const float*)d_in[18];
    const float* c1_b   = (const float*)d_in[19];
    const float* c2_w   = (const float*)d_in[20];
    float* out = (float*)d_out;

    egnn_kernel<<<B_, 2 * N_>>>(data, emb_w, ein_w, ein_b, eout_w, eout_b,
                                fc_w, fc_b, e1_w, e1_b, e2_w, e2_b,
                                n1_w, n1_b, n2_w, n2_b, c1_w, c1_b, c2_w, out);
}

// round 10
// speedup vs baseline: 1.3776x; 1.3075x over previous
#include <cuda_runtime.h>

// GraphVampNet EGNN, sm_103a. Round 10: R7 structure (pair-split, 2-edge
// pairing, two-pointer partner GEMVs, all-layer weights resident, 3 CTAs/SM)
// + fma.rn.f32x2 packing of every GEMV chain (weights loaded as u64 pairs
// straight from smem; exact fp32 semantics).
// B=512 frames, N=128 nodes, K=16 neighbors (j=(i+d)&127), H=16, NL=4, NC=6.

#define B_  512
#define N_  128
#define K_  16
#define H_  16
#define NC_ 6
#define NL_ 4

#define SZ_E1 (34*16)
#define SZ_E2 (16*16)
#define SZ_N1 (32*16)
#define SZ_N2 (16*16)
#define SZ_C1 (16*16)
#define SZ_C2 (16)

#define FULL 0xffffffffu
#define HS 20   // node-state row stride (words): 80B = 5*16B -> 16B-aligned rows

typedef unsigned long long u64;

__device__ __forceinline__ float silu_f(float v) {
    return __fdividef(v, 1.0f + __expf(-v));   // MUFU; rel err ~1e-6
}
__device__ __forceinline__ float4 ld4(const float* p) {
    return *reinterpret_cast<const float4*>(p);
}
__device__ __forceinline__ ulonglong2 ldu2(const float* p) {
    return *reinterpret_cast<const ulonglong2*>(p);
}
// ---- f32x2 helpers (dual-fp32; exact fp32 fma/add) ----
__device__ __forceinline__ u64 bc2(float s) {
    u64 r; asm("mov.b64 %0, {%1, %1};" : "=l"(r) : "f"(s)); return r;
}
__device__ __forceinline__ void up2(u64 v, float &x, float &y) {
    asm("mov.b64 {%0, %1}, %2;" : "=f"(x), "=f"(y) : "l"(v));
}
__device__ __forceinline__ void ffma2(u64 &acc, u64 w, u64 s) {
    asm("fma.rn.f32x2 %0, %1, %2, %0;" : "+l"(acc) : "l"(w), "l"(s));
}
__device__ __forceinline__ void fadd2(u64 &acc, u64 a) {
    asm("add.rn.f32x2 %0, %1, %0;" : "+l"(acc) : "l"(a));
}
// acc[0..3] (8 outs) += s2 * w[0..7]   (2x LDS.128 + 4 FFMA2)
__device__ __forceinline__ void pfma8(u64 (&A)[4], u64 s2, const float* w) {
    ulonglong2 w0 = ldu2(w), w1 = ldu2(w + 4);
    ffma2(A[0], w0.x, s2); ffma2(A[1], w0.y, s2);
    ffma2(A[2], w1.x, s2); ffma2(A[3], w1.y, s2);
}
// two edges share one weight-row load (2x LDS.128 + 8 FFMA2)
__device__ __forceinline__ void pfma8x2(u64 (&A)[4], u64 (&B)[4],
                                        u64 sa, u64 sb, const float* w) {
    ulonglong2 w0 = ldu2(w), w1 = ldu2(w + 4);
    ffma2(A[0], w0.x, sa); ffma2(B[0], w0.x, sb);
    ffma2(A[1], w0.y, sa); ffma2(B[1], w0.y, sb);
    ffma2(A[2], w1.x, sa); ffma2(B[2], w1.x, sb);
    ffma2(A[3], w1.y, sa); ffma2(B[3], w1.y, sb);
}
__device__ __forceinline__ void pbias8(u64 (&A)[4], const float* p) {
    ulonglong2 b0 = ldu2(p), b1 = ldu2(p + 4);
    A[0] = b0.x; A[1] = b0.y; A[2] = b1.x; A[3] = b1.y;
}
__device__ __forceinline__ void unp8(const u64 (&A)[4], float (&o)[8]) {
    up2(A[0], o[0], o[1]); up2(A[1], o[2], o[3]);
    up2(A[2], o[4], o[5]); up2(A[3], o[6], o[7]);
}
__device__ __forceinline__ void load16(float (&r)[16], const float* p) {
    float4 v0 = ld4(p), v1 = ld4(p+4), v2 = ld4(p+8), v3 = ld4(p+12);
    r[0]=v0.x; r[1]=v0.y; r[2]=v0.z; r[3]=v0.w;
    r[4]=v1.x; r[5]=v1.y; r[6]=v1.z; r[7]=v1.w;
    r[8]=v2.x; r[9]=v2.y; r[10]=v2.z; r[11]=v2.w;
    r[12]=v3.x; r[13]=v3.y; r[14]=v3.z; r[15]=v3.w;
}
__device__ __forceinline__ void st8(float* p, const float (&a)[8]) {
    *reinterpret_cast<float4*>(p)     = make_float4(a[0], a[1], a[2], a[3]);
    *reinterpret_cast<float4*>(p + 4) = make_float4(a[4], a[5], a[6], a[7]);
}
__device__ __forceinline__ void stu2(float* p, const u64 (&A)[4]) {
    ulonglong2 v0; v0.x = A[0]; v0.y = A[1];
    ulonglong2 v1; v1.x = A[2]; v1.y = A[3];
    reinterpret_cast<ulonglong2*>(p)[0] = v0;
    reinterpret_cast<ulonglong2*>(p + 4)[0] = v1;
}

__global__ void __launch_bounds__(2 * N_, 3)
egnn_kernel(const float* __restrict__ data,      // [B, N, 3+N]
            const float* __restrict__ emb_w,     // [N, H]
            const float* __restrict__ ein_w, const float* __restrict__ ein_b,
            const float* __restrict__ eout_w, const float* __restrict__ eout_b,
            const float* __restrict__ fc_w,  const float* __restrict__ fc_b,
            const float* __restrict__ e1_w,  const float* __restrict__ e1_b,
            const float* __restrict__ e2_w,  const float* __restrict__ e2_b,
            const float* __restrict__ n1_w,  const float* __restrict__ n1_b,
            const float* __restrict__ n2_w,  const float* __restrict__ n2_b,
            const float* __restrict__ c1_w,  const float* __restrict__ c1_b,
            const float* __restrict__ c2_w,
            float* __restrict__ out)             // [B, NC]
{
    const int b   = blockIdx.x;
    const int tid = threadIdx.x;
    const int i   = tid >> 1;        // node 0..127
    const int e   = tid & 1;         // lane within pair
    const int co  = e * 8;           // owned output-column slice base

    __shared__ __align__(16) float s_h[N_][HS];   // pair-private node features
    __shared__ __align__(16) float s_y[N_][HS];   // e1 neighbor-half (shared)
    __shared__ __align__(16) float4 s_x4[N_];     // coords (shared)

    __shared__ __align__(16) float w_e1[NL_ * SZ_E1], w_e2[NL_ * SZ_E2];
    __shared__ __align__(16) float w_n1[NL_ * SZ_N1], w_n2[NL_ * SZ_N2];
    __shared__ __align__(16) float w_c1[NL_ * SZ_C1], w_c2[NL_ * SZ_C2];
    __shared__ __align__(16) float b_e1[NL_ * 16], b_e2[NL_ * 16];
    __shared__ __align__(16) float b_n1[NL_ * 16], b_n2[NL_ * 16], b_c1[NL_ * 16];
    __shared__ __align__(16) float s_ein[16 * 16], sb_ein[16];
    __shared__ __align__(16) float s_eout[16 * 16], sb_eout[16];
    __shared__ float s_fc[16 * NC_], sb_fc[NC_];
    __shared__ float s_pool[H_];

    const int NT = 2 * N_;
    for (int t = tid; t < NL_ * SZ_E1; t += NT) w_e1[t] = e1_w[t];
    for (int t = tid; t < NL_ * SZ_E2; t += NT) w_e2[t] = e2_w[t];
    for (int t = tid; t < NL_ * SZ_N1; t += NT) w_n1[t] = n1_w[t];
    for (int t = tid; t < NL_ * SZ_N2; t += NT) w_n2[t] = n2_w[t];
    for (int t = tid; t < NL_ * SZ_C1; t += NT) w_c1[t] = c1_w[t];
    for (int t = tid; t < NL_ * SZ_C2; t += NT) w_c2[t] = c2_w[t];
    for (int t = tid; t < NL_ * 16; t += NT) {
        b_e1[t] = e1_b[t]; b_e2[t] = e2_b[t];
        b_n1[t] = n1_b[t]; b_n2[t] = n2_b[t]; b_c1[t] = c1_b[t];
    }
    for (int t = tid; t < 16 * 16; t += NT) { s_ein[t] = ein_w[t]; s_eout[t] = eout_w[t]; }
    if (tid < 16) { sb_ein[tid] = ein_b[tid]; sb_eout[tid] = eout_b[tid]; }
    for (int t = tid; t < 16 * NC_; t += NT) s_fc[t] = fc_w[t];
    if (tid < NC_) sb_fc[tid] = fc_b[tid];

    float xi0, xi1, xi2;
    {
        const float* dptr = data + ((size_t)b * N_ + i) * (3 + N_);
        xi0 = dptr[0]; xi1 = dptr[1]; xi2 = dptr[2];
    }
    __syncthreads();

    // ---- init: h = emb @ ein_w + ein_b  (pair splits 16 outputs 8/8) ----
    {
        u64 acc[4];
        pbias8(acc, sb_ein + co);
        const float* er = emb_w + i * H_;
        #pragma unroll
        for (int k = 0; k < 16; ++k) pfma8(acc, bc2(er[k]), s_ein + k * 16 + co);
        stu2(&s_h[i][co], acc);
        if (e == 0) s_x4[i] = make_float4(xi0, xi1, xi2, 0.0f);
    }
    __syncthreads();

    // ---- E_GCL layers ----
    #pragma unroll 1
    for (int l = 0; l < NL_; ++l) {
        const float* We1c = w_e1 + l * SZ_E1 + co;   // col-sliced e1 weights
        const float* Be2  = b_e2 + l * 16 + co;
        const float* Bc1  = b_c1 + l * 16 + co;
        const float* E2o = w_e2 + l * SZ_E2 + co * 16       + co;
        const float* E2x = w_e2 + l * SZ_E2 + (8 - co) * 16 + co;
        const float* C1o = w_c1 + l * SZ_C1 + co * 16       + co;
        const float* C1x = w_c1 + l * SZ_C1 + (8 - co) * 16 + co;

        // Phase A (per node): pre (packed regs) = bias + e_attr row + h_i @
        // rows0-15 (own cols); y_i = h_i @ rows16-31 (own cols) -> s_y
        u64 pre[4];
        {
            float hf[16]; load16(hf, &s_h[i][0]);
            pbias8(pre, b_e1 + l * 16 + co);
            pfma8(pre, bc2(1.0f), We1c + 33 * 16);
            u64 yq[4] = {0, 0, 0, 0};
            #pragma unroll
            for (int k = 0; k < 16; ++k) {
                const u64 s2 = bc2(hf[k]);
                pfma8(pre, s2, We1c + k * 16);
                pfma8(yq,  s2, We1c + (16 + k) * 16);
            }
            stu2(&s_y[i][co], yq);
        }
        __syncthreads();   // s_y + s_x (from prev layer) visible

        float accm[8] = {0,0,0,0,0,0,0,0};
        float ax0 = 0.f, ax1 = 0.f, ax2 = 0.f;

        #pragma unroll 1
        for (int it = 0; it < 8; ++it) {
            const int d  = 1 + 2 * it;
            const int j0 = (i + d)     & (N_ - 1);
            const int j1 = (i + d + 1) & (N_ - 1);
            float4 xj0 = s_x4[j0];
            float4 xj1 = s_x4[j1];
            const float d00 = xi0-xj0.x, d01 = xi1-xj0.y, d02 = xi2-xj0.z;
            const float d10 = xi0-xj1.x, d11 = xi1-xj1.y, d12 = xi2-xj1.z;
            const float rad0 = fmaf(d00,d00, fmaf(d01,d01, d02*d02));
            const float rad1 = fmaf(d10,d10, fmaf(d11,d11, d12*d12));

            // e1: a = silu(pre + y_j + rad * w_row32)   (own 8 cols, packed)
            float a0[8], a1[8];
            {
                ulonglong2 w32a = ldu2(We1c + 32*16), w32b = ldu2(We1c + 32*16 + 4);
                ulonglong2 ya = ldu2(&s_y[j0][co]), yb = ldu2(&s_y[j0][co+4]);
                ulonglong2 za = ldu2(&s_y[j1][co]), zb = ldu2(&s_y[j1][co+4]);
                const u64 r0 = bc2(rad0), r1 = bc2(rad1);
                u64 A[4] = {ya.x, ya.y, yb.x, yb.y};
                u64 Bv[4] = {za.x, za.y, zb.x, zb.y};
                fadd2(A[0], pre[0]); fadd2(A[1], pre[1]);
                fadd2(A[2], pre[2]); fadd2(A[3], pre[3]);
                fadd2(Bv[0], pre[0]); fadd2(Bv[1], pre[1]);
                fadd2(Bv[2], pre[2]); fadd2(Bv[3], pre[3]);
                ffma2(A[0], w32a.x, r0); ffma2(A[1], w32a.y, r0);
                ffma2(A[2], w32b.x, r0); ffma2(A[3], w32b.y, r0);
                ffma2(Bv[0], w32a.x, r1); ffma2(Bv[1], w32a.y, r1);
                ffma2(Bv[2], w32b.x, r1); ffma2(Bv[3], w32b.y, r1);
                unp8(A, a0); unp8(Bv, a1);
                #pragma unroll
                for (int o = 0; o < 8; ++o) { a0[o] = silu_f(a0[o]); a1[o] = silu_f(a1[o]); }
            }

            // e2: m = silu(a_full @ We2 + b); partner half via shfl_xor
            float m0[8], m1[8];
            {
                u64 M0[4], M1[4];
                pbias8(M0, Be2);
                M1[0]=M0[0]; M1[1]=M0[1]; M1[2]=M0[2]; M1[3]=M0[3];
                #pragma unroll
                for (int r = 0; r < 8; ++r)
                    pfma8x2(M0, M1, bc2(a0[r]), bc2(a1[r]), E2o + r * 16);
                #pragma unroll
                for (int r = 0; r < 8; ++r) {
                    const float s0 = __shfl_xor_sync(FULL, a0[r], 1);
                    const float s1 = __shfl_xor_sync(FULL, a1[r], 1);
                    pfma8x2(M0, M1, bc2(s0), bc2(s1), E2x + r * 16);
                }
                unp8(M0, m0); unp8(M1, m1);
            }
            #pragma unroll
            for (int o = 0; o < 8; ++o) {
                m0[o] = silu_f(m0[o]); m1[o] = silu_f(m1[o]);
                accm[o] += m0[o] + m1[o];
            }

            // coord_mlp: t = silu(m_full @ Wc1 + b) . Wc2  (packed; reuse a)
            {
                u64 T0[4], T1[4];
                pbias8(T0, Bc1);
                T1[0]=T0[0]; T1[1]=T0[1]; T1[2]=T0[2]; T1[3]=T0[3];
                #pragma unroll
                for (int r = 0; r < 8; ++r)
                    pfma8x2(T0, T1, bc2(m0[r]), bc2(m1[r]), C1o + r * 16);
                #pragma unroll
                for (int r = 0; r < 8; ++r) {
                    const float s0 = __shfl_xor_sync(FULL, m0[r], 1);
                    const float s1 = __shfl_xor_sync(FULL, m1[r], 1);
                    pfma8x2(T0, T1, bc2(s0), bc2(s1), C1x + r * 16);
                }
                unp8(T0, a0); unp8(T1, a1);
            }
            float t0, t1;
            {
                float4 w0 = ld4(w_c2 + l * SZ_C2 + co);
                float4 w1 = ld4(w_c2 + l * SZ_C2 + co + 4);
                t0 = silu_f(a0[0]) * w0.x;
                t0 = fmaf(silu_f(a0[1]), w0.y, t0);
                t0 = fmaf(silu_f(a0[2]), w0.z, t0);
                t0 = fmaf(silu_f(a0[3]), w0.w, t0);
                t0 = fmaf(silu_f(a0[4]), w1.x, t0);
                t0 = fmaf(silu_f(a0[5]), w1.y, t0);
                t0 = fmaf(silu_f(a0[6]), w1.z, t0);
                t0 = fmaf(silu_f(a0[7]), w1.w, t0);
                t1 = silu_f(a1[0]) * w0.x;
                t1 = fmaf(silu_f(a1[1]), w0.y, t1);
                t1 = fmaf(silu_f(a1[2]), w0.z, t1);
                t1 = fmaf(silu_f(a1[3]), w0.w, t1);
                t1 = fmaf(silu_f(a1[4]), w1.x, t1);
                t1 = fmaf(silu_f(a1[5]), w1.y, t1);
                t1 = fmaf(silu_f(a1[6]), w1.z, t1);
                t1 = fmaf(silu_f(a1[7]), w1.w, t1);
            }
            t0 += __shfl_xor_sync(FULL, t0, 1);   // partner holds other 8 dims
            t1 += __shfl_xor_sync(FULL, t1, 1);

            ax0 = fmaf(d00, t0, fmaf(d10, t1, ax0));
            ax1 = fmaf(d01, t0, fmaf(d11, t1, ax1));
            ax2 = fmaf(d02, t0, fmaf(d12, t1, ax2));
        }

        xi0 = fmaf(ax0, 0.0625f, xi0);   // cnt == 16
        xi1 = fmaf(ax1, 0.0625f, xi1);
        xi2 = fmaf(ax2, 0.0625f, xi2);

        __syncthreads();   // all Phase-B reads of s_y / s_x done block-wide

        // Phase C: node_mlp (pair-split 8/8, packed); exchanges via shfl_xor
        {
            const float* Wn1c = w_n1 + l * SZ_N1 + co;
            const float* N1o = w_n1 + l * SZ_N1 + (16 + co) * 16     + co;
            const float* N1x = w_n1 + l * SZ_N1 + (16 + 8 - co) * 16 + co;
            const float* N2o = w_n2 + l * SZ_N2 + co * 16       + co;
            const float* N2x = w_n2 + l * SZ_N2 + (8 - co) * 16 + co;

            float hf[16]; load16(hf, &s_h[i][0]);   // old h (pair-private)
            float na[8];
            {
                u64 NA[4];
                pbias8(NA, b_n1 + l * 16 + co);
                #pragma unroll
                for (int k = 0; k < 16; ++k) pfma8(NA, bc2(hf[k]), Wn1c + k * 16);
                #pragma unroll
                for (int r = 0; r < 8; ++r) pfma8(NA, bc2(accm[r]), N1o + r * 16);
                #pragma unroll
                for (int r = 0; r < 8; ++r)
                    pfma8(NA, bc2(__shfl_xor_sync(FULL, accm[r], 1)), N1x + r * 16);
                unp8(NA, na);
            }
            #pragma unroll
            for (int o = 0; o < 8; ++o) na[o] = silu_f(na[o]);

            float hb[8];
            {
                u64 HB[4];
                pbias8(HB, b_n2 + l * 16 + co);
                #pragma unroll
                for (int r = 0; r < 8; ++r) pfma8(HB, bc2(na[r]), N2o + r * 16);
                #pragma unroll
                for (int r = 0; r < 8; ++r)
                    pfma8(HB, bc2(__shfl_xor_sync(FULL, na[r], 1)), N2x + r * 16);
                unp8(HB, hb);
            }
            {   // residual from own smem slice
                float4 r0 = ld4(&s_h[i][co]), r1 = ld4(&s_h[i][co + 4]);
                hb[0] += r0.x; hb[1] += r0.y; hb[2] += r0.z; hb[3] += r0.w;
                hb[4] += r1.x; hb[5] += r1.y; hb[6] += r1.z; hb[7] += r1.w;
            }
            __syncwarp();          // partner's reads of old s_h row complete
            st8(&s_h[i][co], hb);
            if (e == 0) s_x4[i] = make_float4(xi0, xi1, xi2, 0.0f);
        }
        __syncwarp();
    }

    // ---- embedding_out + pooling ----
    {
        float hf[16]; load16(hf, &s_h[i][0]);
        u64 HO[4];
        pbias8(HO, sb_eout + co);
        #pragma unroll
        for (int k = 0; k < 16; ++k) pfma8(HO, bc2(hf[k]), s_eout + k * 16 + co);
        __syncthreads();
        stu2(&s_h[i][co], HO);
    }
    __syncthreads();

    if (tid < H_) {
        float s = 0.0f;
        for (int j = 0; j < N_; ++j) s += s_h[j][tid];
        s_pool[tid] = s * (1.0f / (float)N_);
    }
    __syncthreads();

    if (tid == 0) {
        float logit[NC_];
        float mx = -1e30f;
        #pragma unroll
        for (int c = 0; c < NC_; ++c) {
            float s = sb_fc[c];
            #pragma unroll
            for (int k = 0; k < H_; ++k) s = fmaf(s_pool[k], s_fc[k * NC_ + c], s);
            logit[c] = s;
            mx = fmaxf(mx, s);
        }
        float den = 0.0f;
        float ev[NC_];
        #pragma unroll
        for (int c = 0; c < NC_; ++c) { ev[c] = expf(logit[c] - mx); den += ev[c]; }
        const float inv = 1.0f / den;
        #pragma unroll
        for (int c = 0; c < NC_; ++c) out[b * NC_ + c] = ev[c] * inv;
    }
}

extern "C" void kernel_launch(void* const* d_in, const int* in_sizes, int n_in,
                              void* d_out, int out_size)
{
    const float* data   = (const float*)d_in[0];
    const float* emb_w  = (const float*)d_in[3];
    const float* ein_w  = (const float*)d_in[4];
    const float* ein_b  = (const float*)d_in[5];
    const float* eout_w = (const float*)d_in[6];
    const float* eout_b = (const float*)d_in[7];
    const float* fc_w   = (const float*)d_in[8];
    const float* fc_b   = (const float*)d_in[9];
    const float* e1_w   = (const float*)d_in[10];
    const float* e1_b   = (const float*)d_in[11];
    const float* e2_w   = (const float*)d_in[12];
    const float* e2_b   = (const float*)d_in[13];
    const float* n1_w   = (const float*)d_in[14];
    const float* n1_b   = (const float*)d_in[15];
    const float* n2_w   = (const float*)d_in[16];
    const float* n2_b   = (const float*)d_in[17];
    const float* c1_w   = (const float*)d_in[18];
    const float* c1_b   = (const float*)d_in[19];
    const float* c2_w   = (const float*)d_in[20];
    float* out = (float*)d_out;

    egnn_kernel<<<B_, 2 * N_>>>(data, emb_w, ein_w, ein_b, eout_w, eout_b,
                                fc_w, fc_b, e1_w, e1_b, e2_w, e2_b,
                                n1_w, n1_b, n2_w, n2_b, c1_w, c1_b, c2_w, out);
}

// round 11
// speedup vs baseline: 1.6244x; 1.1791x over previous
#include <cuda_runtime.h>

// GraphVampNet EGNN, sm_103a. Round 11: EXACT R10 compute (pair-split, 2-edge
// pairing, two-pointer partner GEMVs, f32x2-packed chains) with occupancy
// FORCED to 2 CTAs/SM (smem padding to ~80KB + launch_bounds(256,2)).
// Rationale: L1-saturated during wave 1; 3 CTA/SM gives makespan 2x3t, 2 CTA/SM
// gives 2x2t (work-steal balance 86.5%) -> ~1.5x on the L1-bound portion.
// B=512 frames, N=128 nodes, K=16 neighbors (j=(i+d)&127), H=16, NL=4, NC=6.

#define B_  512
#define N_  128
#define K_  16
#define H_  16
#define NC_ 6
#define NL_ 4

#define SZ_E1 (34*16)
#define SZ_E2 (16*16)
#define SZ_N1 (32*16)
#define SZ_N2 (16*16)
#define SZ_C1 (16*16)
#define SZ_C2 (16)

// Pad an otherwise-used shared array so CTA smem ~= 80.5KB: 228KB/SM -> 2 CTAs.
#define SMEM_PAD 6144

#define FULL 0xffffffffu
#define HS 20   // node-state row stride (words): 80B = 5*16B -> 16B-aligned rows

typedef unsigned long long u64;

__device__ __forceinline__ float silu_f(float v) {
    return __fdividef(v, 1.0f + __expf(-v));   // MUFU; rel err ~1e-6
}
__device__ __forceinline__ float4 ld4(const float* p) {
    return *reinterpret_cast<const float4*>(p);
}
__device__ __forceinline__ ulonglong2 ldu2(const float* p) {
    return *reinterpret_cast<const ulonglong2*>(p);
}
// ---- f32x2 helpers (dual-fp32; exact fp32 fma/add) ----
__device__ __forceinline__ u64 bc2(float s) {
    u64 r; asm("mov.b64 %0, {%1, %1};" : "=l"(r) : "f"(s)); return r;
}
__device__ __forceinline__ void up2(u64 v, float &x, float &y) {
    asm("mov.b64 {%0, %1}, %2;" : "=f"(x), "=f"(y) : "l"(v));
}
__device__ __forceinline__ void ffma2(u64 &acc, u64 w, u64 s) {
    asm("fma.rn.f32x2 %0, %1, %2, %0;" : "+l"(acc) : "l"(w), "l"(s));
}
__device__ __forceinline__ void fadd2(u64 &acc, u64 a) {
    asm("add.rn.f32x2 %0, %1, %0;" : "+l"(acc) : "l"(a));
}
// acc[0..3] (8 outs) += s2 * w[0..7]   (2x LDS.128 + 4 FFMA2)
__device__ __forceinline__ void pfma8(u64 (&A)[4], u64 s2, const float* w) {
    ulonglong2 w0 = ldu2(w), w1 = ldu2(w + 4);
    ffma2(A[0], w0.x, s2); ffma2(A[1], w0.y, s2);
    ffma2(A[2], w1.x, s2); ffma2(A[3], w1.y, s2);
}
// two edges share one weight-row load (2x LDS.128 + 8 FFMA2)
__device__ __forceinline__ void pfma8x2(u64 (&A)[4], u64 (&B)[4],
                                        u64 sa, u64 sb, const float* w) {
    ulonglong2 w0 = ldu2(w), w1 = ldu2(w + 4);
    ffma2(A[0], w0.x, sa); ffma2(B[0], w0.x, sb);
    ffma2(A[1], w0.y, sa); ffma2(B[1], w0.y, sb);
    ffma2(A[2], w1.x, sa); ffma2(B[2], w1.x, sb);
    ffma2(A[3], w1.y, sa); ffma2(B[3], w1.y, sb);
}
__device__ __forceinline__ void pbias8(u64 (&A)[4], const float* p) {
    ulonglong2 b0 = ldu2(p), b1 = ldu2(p + 4);
    A[0] = b0.x; A[1] = b0.y; A[2] = b1.x; A[3] = b1.y;
}
__device__ __forceinline__ void unp8(const u64 (&A)[4], float (&o)[8]) {
    up2(A[0], o[0], o[1]); up2(A[1], o[2], o[3]);
    up2(A[2], o[4], o[5]); up2(A[3], o[6], o[7]);
}
__device__ __forceinline__ void load16(float (&r)[16], const float* p) {
    float4 v0 = ld4(p), v1 = ld4(p+4), v2 = ld4(p+8), v3 = ld4(p+12);
    r[0]=v0.x; r[1]=v0.y; r[2]=v0.z; r[3]=v0.w;
    r[4]=v1.x; r[5]=v1.y; r[6]=v1.z; r[7]=v1.w;
    r[8]=v2.x; r[9]=v2.y; r[10]=v2.z; r[11]=v2.w;
    r[12]=v3.x; r[13]=v3.y; r[14]=v3.z; r[15]=v3.w;
}
__device__ __forceinline__ void st8(float* p, const float (&a)[8]) {
    *reinterpret_cast<float4*>(p)     = make_float4(a[0], a[1], a[2], a[3]);
    *reinterpret_cast<float4*>(p + 4) = make_float4(a[4], a[5], a[6], a[7]);
}
__device__ __forceinline__ void stu2(float* p, const u64 (&A)[4]) {
    ulonglong2 v0; v0.x = A[0]; v0.y = A[1];
    ulonglong2 v1; v1.x = A[2]; v1.y = A[3];
    reinterpret_cast<ulonglong2*>(p)[0] = v0;
    reinterpret_cast<ulonglong2*>(p + 4)[0] = v1;
}

__global__ void __launch_bounds__(2 * N_, 2)
egnn_kernel(const float* __restrict__ data,      // [B, N, 3+N]
            const float* __restrict__ emb_w,     // [N, H]
            const float* __restrict__ ein_w, const float* __restrict__ ein_b,
            const float* __restrict__ eout_w, const float* __restrict__ eout_b,
            const float* __restrict__ fc_w,  const float* __restrict__ fc_b,
            const float* __restrict__ e1_w,  const float* __restrict__ e1_b,
            const float* __restrict__ e2_w,  const float* __restrict__ e2_b,
            const float* __restrict__ n1_w,  const float* __restrict__ n1_b,
            const float* __restrict__ n2_w,  const float* __restrict__ n2_b,
            const float* __restrict__ c1_w,  const float* __restrict__ c1_b,
            const float* __restrict__ c2_w,
            float* __restrict__ out)             // [B, NC]
{
    const int b   = blockIdx.x;
    const int tid = threadIdx.x;
    const int i   = tid >> 1;        // node 0..127
    const int e   = tid & 1;         // lane within pair
    const int co  = e * 8;           // owned output-column slice base

    __shared__ __align__(16) float s_h[N_][HS];   // pair-private node features
    __shared__ __align__(16) float s_y[N_][HS];   // e1 neighbor-half (shared)
    __shared__ __align__(16) float4 s_x4[N_];     // coords (shared)

    // w_e1 carries SMEM_PAD unused tail words: occupancy limiter (2 CTAs/SM)
    __shared__ __align__(16) float w_e1[NL_ * SZ_E1 + SMEM_PAD], w_e2[NL_ * SZ_E2];
    __shared__ __align__(16) float w_n1[NL_ * SZ_N1], w_n2[NL_ * SZ_N2];
    __shared__ __align__(16) float w_c1[NL_ * SZ_C1], w_c2[NL_ * SZ_C2];
    __shared__ __align__(16) float b_e1[NL_ * 16], b_e2[NL_ * 16];
    __shared__ __align__(16) float b_n1[NL_ * 16], b_n2[NL_ * 16], b_c1[NL_ * 16];
    __shared__ __align__(16) float s_ein[16 * 16], sb_ein[16];
    __shared__ __align__(16) float s_eout[16 * 16], sb_eout[16];
    __shared__ float s_fc[16 * NC_], sb_fc[NC_];
    __shared__ float s_pool[H_];

    const int NT = 2 * N_;
    for (int t = tid; t < NL_ * SZ_E1; t += NT) w_e1[t] = e1_w[t];
    for (int t = tid; t < NL_ * SZ_E2; t += NT) w_e2[t] = e2_w[t];
    for (int t = tid; t < NL_ * SZ_N1; t += NT) w_n1[t] = n1_w[t];
    for (int t = tid; t < NL_ * SZ_N2; t += NT) w_n2[t] = n2_w[t];
    for (int t = tid; t < NL_ * SZ_C1; t += NT) w_c1[t] = c1_w[t];
    for (int t = tid; t < NL_ * SZ_C2; t += NT) w_c2[t] = c2_w[t];
    for (int t = tid; t < NL_ * 16; t += NT) {
        b_e1[t] = e1_b[t]; b_e2[t] = e2_b[t];
        b_n1[t] = n1_b[t]; b_n2[t] = n2_b[t]; b_c1[t] = c1_b[t];
    }
    for (int t = tid; t < 16 * 16; t += NT) { s_ein[t] = ein_w[t]; s_eout[t] = eout_w[t]; }
    if (tid < 16) { sb_ein[tid] = ein_b[tid]; sb_eout[tid] = eout_b[tid]; }
    for (int t = tid; t < 16 * NC_; t += NT) s_fc[t] = fc_w[t];
    if (tid < NC_) sb_fc[tid] = fc_b[tid];

    float xi0, xi1, xi2;
    {
        const float* dptr = data + ((size_t)b * N_ + i) * (3 + N_);
        xi0 = dptr[0]; xi1 = dptr[1]; xi2 = dptr[2];
    }
    __syncthreads();

    // ---- init: h = emb @ ein_w + ein_b  (pair splits 16 outputs 8/8) ----
    {
        u64 acc[4];
        pbias8(acc, sb_ein + co);
        const float* er = emb_w + i * H_;
        #pragma unroll
        for (int k = 0; k < 16; ++k) pfma8(acc, bc2(er[k]), s_ein + k * 16 + co);
        stu2(&s_h[i][co], acc);
        if (e == 0) s_x4[i] = make_float4(xi0, xi1, xi2, 0.0f);
    }
    __syncthreads();

    // ---- E_GCL layers ----
    #pragma unroll 1
    for (int l = 0; l < NL_; ++l) {
        const float* We1c = w_e1 + l * SZ_E1 + co;   // col-sliced e1 weights
        const float* Be2  = b_e2 + l * 16 + co;
        const float* Bc1  = b_c1 + l * 16 + co;
        const float* E2o = w_e2 + l * SZ_E2 + co * 16       + co;
        const float* E2x = w_e2 + l * SZ_E2 + (8 - co) * 16 + co;
        const float* C1o = w_c1 + l * SZ_C1 + co * 16       + co;
        const float* C1x = w_c1 + l * SZ_C1 + (8 - co) * 16 + co;

        // Phase A (per node): pre (packed regs) = bias + e_attr row + h_i @
        // rows0-15 (own cols); y_i = h_i @ rows16-31 (own cols) -> s_y
        u64 pre[4];
        {
            float hf[16]; load16(hf, &s_h[i][0]);
            pbias8(pre, b_e1 + l * 16 + co);
            pfma8(pre, bc2(1.0f), We1c + 33 * 16);
            u64 yq[4] = {0, 0, 0, 0};
            #pragma unroll
            for (int k = 0; k < 16; ++k) {
                const u64 s2 = bc2(hf[k]);
                pfma8(pre, s2, We1c + k * 16);
                pfma8(yq,  s2, We1c + (16 + k) * 16);
            }
            stu2(&s_y[i][co], yq);
        }
        __syncthreads();   // s_y + s_x (from prev layer) visible

        float accm[8] = {0,0,0,0,0,0,0,0};
        float ax0 = 0.f, ax1 = 0.f, ax2 = 0.f;

        #pragma unroll 1
        for (int it = 0; it < 8; ++it) {
            const int d  = 1 + 2 * it;
            const int j0 = (i + d)     & (N_ - 1);
            const int j1 = (i + d + 1) & (N_ - 1);
            float4 xj0 = s_x4[j0];
            float4 xj1 = s_x4[j1];
            const float d00 = xi0-xj0.x, d01 = xi1-xj0.y, d02 = xi2-xj0.z;
            const float d10 = xi0-xj1.x, d11 = xi1-xj1.y, d12 = xi2-xj1.z;
            const float rad0 = fmaf(d00,d00, fmaf(d01,d01, d02*d02));
            const float rad1 = fmaf(d10,d10, fmaf(d11,d11, d12*d12));

            // e1: a = silu(pre + y_j + rad * w_row32)   (own 8 cols, packed)
            float a0[8], a1[8];
            {
                ulonglong2 w32a = ldu2(We1c + 32*16), w32b = ldu2(We1c + 32*16 + 4);
                ulonglong2 ya = ldu2(&s_y[j0][co]), yb = ldu2(&s_y[j0][co+4]);
                ulonglong2 za = ldu2(&s_y[j1][co]), zb = ldu2(&s_y[j1][co+4]);
                const u64 r0 = bc2(rad0), r1 = bc2(rad1);
                u64 A[4] = {ya.x, ya.y, yb.x, yb.y};
                u64 Bv[4] = {za.x, za.y, zb.x, zb.y};
                fadd2(A[0], pre[0]); fadd2(A[1], pre[1]);
                fadd2(A[2], pre[2]); fadd2(A[3], pre[3]);
                fadd2(Bv[0], pre[0]); fadd2(Bv[1], pre[1]);
                fadd2(Bv[2], pre[2]); fadd2(Bv[3], pre[3]);
                ffma2(A[0], w32a.x, r0); ffma2(A[1], w32a.y, r0);
                ffma2(A[2], w32b.x, r0); ffma2(A[3], w32b.y, r0);
                ffma2(Bv[0], w32a.x, r1); ffma2(Bv[1], w32a.y, r1);
                ffma2(Bv[2], w32b.x, r1); ffma2(Bv[3], w32b.y, r1);
                unp8(A, a0); unp8(Bv, a1);
                #pragma unroll
                for (int o = 0; o < 8; ++o) { a0[o] = silu_f(a0[o]); a1[o] = silu_f(a1[o]); }
            }

            // e2: m = silu(a_full @ We2 + b); partner half via shfl_xor
            float m0[8], m1[8];
            {
                u64 M0[4], M1[4];
                pbias8(M0, Be2);
                M1[0]=M0[0]; M1[1]=M0[1]; M1[2]=M0[2]; M1[3]=M0[3];
                #pragma unroll
                for (int r = 0; r < 8; ++r)
                    pfma8x2(M0, M1, bc2(a0[r]), bc2(a1[r]), E2o + r * 16);
                #pragma unroll
                for (int r = 0; r < 8; ++r) {
                    const float s0 = __shfl_xor_sync(FULL, a0[r], 1);
                    const float s1 = __shfl_xor_sync(FULL, a1[r], 1);
                    pfma8x2(M0, M1, bc2(s0), bc2(s1), E2x + r * 16);
                }
                unp8(M0, m0); unp8(M1, m1);
            }
            #pragma unroll
            for (int o = 0; o < 8; ++o) {
                m0[o] = silu_f(m0[o]); m1[o] = silu_f(m1[o]);
                accm[o] += m0[o] + m1[o];
            }

            // coord_mlp: t = silu(m_full @ Wc1 + b) . Wc2  (packed; reuse a)
            {
                u64 T0[4], T1[4];
                pbias8(T0, Bc1);
                T1[0]=T0[0]; T1[1]=T0[1]; T1[2]=T0[2]; T1[3]=T0[3];
                #pragma unroll
                for (int r = 0; r < 8; ++r)
                    pfma8x2(T0, T1, bc2(m0[r]), bc2(m1[r]), C1o + r * 16);
                #pragma unroll
                for (int r = 0; r < 8; ++r) {
                    const float s0 = __shfl_xor_sync(FULL, m0[r], 1);
                    const float s1 = __shfl_xor_sync(FULL, m1[r], 1);
                    pfma8x2(T0, T1, bc2(s0), bc2(s1), C1x + r * 16);
                }
                unp8(T0, a0); unp8(T1, a1);
            }
            float t0, t1;
            {
                float4 w0 = ld4(w_c2 + l * SZ_C2 + co);
                float4 w1 = ld4(w_c2 + l * SZ_C2 + co + 4);
                t0 = silu_f(a0[0]) * w0.x;
                t0 = fmaf(silu_f(a0[1]), w0.y, t0);
                t0 = fmaf(silu_f(a0[2]), w0.z, t0);
                t0 = fmaf(silu_f(a0[3]), w0.w, t0);
                t0 = fmaf(silu_f(a0[4]), w1.x, t0);
                t0 = fmaf(silu_f(a0[5]), w1.y, t0);
                t0 = fmaf(silu_f(a0[6]), w1.z, t0);
                t0 = fmaf(silu_f(a0[7]), w1.w, t0);
                t1 = silu_f(a1[0]) * w0.x;
                t1 = fmaf(silu_f(a1[1]), w0.y, t1);
                t1 = fmaf(silu_f(a1[2]), w0.z, t1);
                t1 = fmaf(silu_f(a1[3]), w0.w, t1);
                t1 = fmaf(silu_f(a1[4]), w1.x, t1);
                t1 = fmaf(silu_f(a1[5]), w1.y, t1);
                t1 = fmaf(silu_f(a1[6]), w1.z, t1);
                t1 = fmaf(silu_f(a1[7]), w1.w, t1);
            }
            t0 += __shfl_xor_sync(FULL, t0, 1);   // partner holds other 8 dims
            t1 += __shfl_xor_sync(FULL, t1, 1);

            ax0 = fmaf(d00, t0, fmaf(d10, t1, ax0));
            ax1 = fmaf(d01, t0, fmaf(d11, t1, ax1));
            ax2 = fmaf(d02, t0, fmaf(d12, t1, ax2));
        }

        xi0 = fmaf(ax0, 0.0625f, xi0);   // cnt == 16
        xi1 = fmaf(ax1, 0.0625f, xi1);
        xi2 = fmaf(ax2, 0.0625f, xi2);

        __syncthreads();   // all Phase-B reads of s_y / s_x done block-wide

        // Phase C: node_mlp (pair-split 8/8, packed); exchanges via shfl_xor
        {
            const float* Wn1c = w_n1 + l * SZ_N1 + co;
            const float* N1o = w_n1 + l * SZ_N1 + (16 + co) * 16     + co;
            const float* N1x = w_n1 + l * SZ_N1 + (16 + 8 - co) * 16 + co;
            const float* N2o = w_n2 + l * SZ_N2 + co * 16       + co;
            const float* N2x = w_n2 + l * SZ_N2 + (8 - co) * 16 + co;

            float hf[16]; load16(hf, &s_h[i][0]);   // old h (pair-private)
            float na[8];
            {
                u64 NA[4];
                pbias8(NA, b_n1 + l * 16 + co);
                #pragma unroll
                for (int k = 0; k < 16; ++k) pfma8(NA, bc2(hf[k]), Wn1c + k * 16);
                #pragma unroll
                for (int r = 0; r < 8; ++r) pfma8(NA, bc2(accm[r]), N1o + r * 16);
                #pragma unroll
                for (int r = 0; r < 8; ++r)
                    pfma8(NA, bc2(__shfl_xor_sync(FULL, accm[r], 1)), N1x + r * 16);
                unp8(NA, na);
            }
            #pragma unroll
            for (int o = 0; o < 8; ++o) na[o] = silu_f(na[o]);

            float hb[8];
            {
                u64 HB[4];
                pbias8(HB, b_n2 + l * 16 + co);
                #pragma unroll
                for (int r = 0; r < 8; ++r) pfma8(HB, bc2(na[r]), N2o + r * 16);
                #pragma unroll
                for (int r = 0; r < 8; ++r)
                    pfma8(HB, bc2(__shfl_xor_sync(FULL, na[r], 1)), N2x + r * 16);
                unp8(HB, hb);
            }
            {   // residual from own smem slice
                float4 r0 = ld4(&s_h[i][co]), r1 = ld4(&s_h[i][co + 4]);
                hb[0] += r0.x; hb[1] += r0.y; hb[2] += r0.z; hb[3] += r0.w;
                hb[4] += r1.x; hb[5] += r1.y; hb[6] += r1.z; hb[7] += r1.w;
            }
            __syncwarp();          // partner's reads of old s_h row complete
            st8(&s_h[i][co], hb);
            if (e == 0) s_x4[i] = make_float4(xi0, xi1, xi2, 0.0f);
        }
        __syncwarp();
    }

    // ---- embedding_out + pooling ----
    {
        float hf[16]; load16(hf, &s_h[i][0]);
        u64 HO[4];
        pbias8(HO, sb_eout + co);
        #pragma unroll
        for (int k = 0; k < 16; ++k) pfma8(HO, bc2(hf[k]), s_eout + k * 16 + co);
        __syncthreads();
        stu2(&s_h[i][co], HO);
    }
    __syncthreads();

    if (tid < H_) {
        float s = 0.0f;
        for (int j = 0; j < N_; ++j) s += s_h[j][tid];
        s_pool[tid] = s * (1.0f / (float)N_);
    }
    __syncthreads();

    if (tid == 0) {
        float logit[NC_];
        float mx = -1e30f;
        #pragma unroll
        for (int c = 0; c < NC_; ++c) {
            float s = sb_fc[c];
            #pragma unroll
            for (int k = 0; k < H_; ++k) s = fmaf(s_pool[k], s_fc[k * NC_ + c], s);
            logit[c] = s;
            mx = fmaxf(mx, s);
        }
        float den = 0.0f;
        float ev[NC_];
        #pragma unroll
        for (int c = 0; c < NC_; ++c) { ev[c] = expf(logit[c] - mx); den += ev[c]; }
        const float inv = 1.0f / den;
        #pragma unroll
        for (int c = 0; c < NC_; ++c) out[b * NC_ + c] = ev[c] * inv;
    }
}

extern "C" void kernel_launch(void* const* d_in, const int* in_sizes, int n_in,
                              void* d_out, int out_size)
{
    const float* data   = (const float*)d_in[0];
    const float* emb_w  = (const float*)d_in[3];
    const float* ein_w  = (const float*)d_in[4];
    const float* ein_b  = (const float*)d_in[5];
    const float* eout_w = (const float*)d_in[6];
    const float* eout_b = (const float*)d_in[7];
    const float* fc_w   = (const float*)d_in[8];
    const float* fc_b   = (const float*)d_in[9];
    const float* e1_w   = (const float*)d_in[10];
    const float* e1_b   = (const float*)d_in[11];
    const float* e2_w   = (const float*)d_in[12];
    const float* e2_b   = (const float*)d_in[13];
    const float* n1_w   = (const float*)d_in[14];
    const float* n1_b   = (const float*)d_in[15];
    const float* n2_w   = (const float*)d_in[16];
    const float* n2_b   = (const float*)d_in[17];
    const float* c1_w   = (const float*)d_in[18];
    const float* c1_b   = (const float*)d_in[19];
    const float* c2_w   = (const float*)d_in[20];
    float* out = (float*)d_out;

    egnn_kernel<<<B_, 2 * N_>>>(data, emb_w, ein_w, ein_b, eout_w, eout_b,
                                fc_w, fc_b, e1_w, e1_b, e2_w, e2_b,
                                n1_w, n1_b, n2_w, n2_b, c1_w, c1_b, c2_w, out);
}

// round 12
// speedup vs baseline: 1.6410x; 1.0102x over previous
#include <cuda_runtime.h>

// GraphVampNet EGNN, sm_103a. Round 12: R11 (pair-split, two-pointer partner
// GEMVs, f32x2 packing, forced 2 CTAs/SM) + 4-edge batching in the edge loop:
// each e2/c1 weight-row LDS.128 pair now feeds 16 FFMA2 across 4 edges.
// B=512 frames, N=128 nodes, K=16 neighbors (j=(i+d)&127), H=16, NL=4, NC=6.

#define B_  512
#define N_  128
#define K_  16
#define H_  16
#define NC_ 6
#define NL_ 4

#define SZ_E1 (34*16)
#define SZ_E2 (16*16)
#define SZ_N1 (32*16)
#define SZ_N2 (16*16)
#define SZ_C1 (16*16)
#define SZ_C2 (16)

// Pad smem so CTA total ~= 80KB: 228KB/SM -> exactly 2 resident CTAs.
#define SMEM_PAD 6144

#define FULL 0xffffffffu
#define HS 20   // node-state row stride (words)

typedef unsigned long long u64;

__device__ __forceinline__ float silu_f(float v) {
    return __fdividef(v, 1.0f + __expf(-v));   // MUFU; rel err ~1e-6
}
__device__ __forceinline__ float4 ld4(const float* p) {
    return *reinterpret_cast<const float4*>(p);
}
__device__ __forceinline__ ulonglong2 ldu2(const float* p) {
    return *reinterpret_cast<const ulonglong2*>(p);
}
// ---- f32x2 helpers ----
__device__ __forceinline__ u64 bc2(float s) {
    u64 r; asm("mov.b64 %0, {%1, %1};" : "=l"(r) : "f"(s)); return r;
}
__device__ __forceinline__ void up2(u64 v, float &x, float &y) {
    asm("mov.b64 {%0, %1}, %2;" : "=f"(x), "=f"(y) : "l"(v));
}
__device__ __forceinline__ void ffma2(u64 &acc, u64 w, u64 s) {
    asm("fma.rn.f32x2 %0, %1, %2, %0;" : "+l"(acc) : "l"(w), "l"(s));
}
__device__ __forceinline__ void fadd2(u64 &acc, u64 a) {
    asm("add.rn.f32x2 %0, %1, %0;" : "+l"(acc) : "l"(a));
}
__device__ __forceinline__ void pfma8(u64 (&A)[4], u64 s2, const float* w) {
    ulonglong2 w0 = ldu2(w), w1 = ldu2(w + 4);
    ffma2(A[0], w0.x, s2); ffma2(A[1], w0.y, s2);
    ffma2(A[2], w1.x, s2); ffma2(A[3], w1.y, s2);
}
// FOUR edges share one weight-row load (2x LDS.128 + 16 FFMA2)
__device__ __forceinline__ void pfma8x4(u64 (&A)[4], u64 (&B)[4],
                                        u64 (&C)[4], u64 (&D)[4],
                                        u64 sa, u64 sb, u64 sc, u64 sd,
                                        const float* w) {
    ulonglong2 w0 = ldu2(w), w1 = ldu2(w + 4);
    ffma2(A[0], w0.x, sa); ffma2(B[0], w0.x, sb);
    ffma2(C[0], w0.x, sc); ffma2(D[0], w0.x, sd);
    ffma2(A[1], w0.y, sa); ffma2(B[1], w0.y, sb);
    ffma2(C[1], w0.y, sc); ffma2(D[1], w0.y, sd);
    ffma2(A[2], w1.x, sa); ffma2(B[2], w1.x, sb);
    ffma2(C[2], w1.x, sc); ffma2(D[2], w1.x, sd);
    ffma2(A[3], w1.y, sa); ffma2(B[3], w1.y, sb);
    ffma2(C[3], w1.y, sc); ffma2(D[3], w1.y, sd);
}
__device__ __forceinline__ void pbias8(u64 (&A)[4], const float* p) {
    ulonglong2 b0 = ldu2(p), b1 = ldu2(p + 4);
    A[0] = b0.x; A[1] = b0.y; A[2] = b1.x; A[3] = b1.y;
}
__device__ __forceinline__ void unp8(const u64 (&A)[4], float (&o)[8]) {
    up2(A[0], o[0], o[1]); up2(A[1], o[2], o[3]);
    up2(A[2], o[4], o[5]); up2(A[3], o[6], o[7]);
}
__device__ __forceinline__ void load16(float (&r)[16], const float* p) {
    float4 v0 = ld4(p), v1 = ld4(p+4), v2 = ld4(p+8), v3 = ld4(p+12);
    r[0]=v0.x; r[1]=v0.y; r[2]=v0.z; r[3]=v0.w;
    r[4]=v1.x; r[5]=v1.y; r[6]=v1.z; r[7]=v1.w;
    r[8]=v2.x; r[9]=v2.y; r[10]=v2.z; r[11]=v2.w;
    r[12]=v3.x; r[13]=v3.y; r[14]=v3.z; r[15]=v3.w;
}
__device__ __forceinline__ void st8(float* p, const float (&a)[8]) {
    *reinterpret_cast<float4*>(p)     = make_float4(a[0], a[1], a[2], a[3]);
    *reinterpret_cast<float4*>(p + 4) = make_float4(a[4], a[5], a[6], a[7]);
}
__device__ __forceinline__ void stu2(float* p, const u64 (&A)[4]) {
    ulonglong2 v0; v0.x = A[0]; v0.y = A[1];
    ulonglong2 v1; v1.x = A[2]; v1.y = A[3];
    reinterpret_cast<ulonglong2*>(p)[0] = v0;
    reinterpret_cast<ulonglong2*>(p + 4)[0] = v1;
}
// e1 for one edge: out = silu(pre + y_j + rad*w32) on own 8 cols
__device__ __forceinline__ void e1_edge(float (&o)[8], const float* yrow,
                                        const u64 (&pre)[4],
                                        ulonglong2 w32a, ulonglong2 w32b,
                                        float rad) {
    ulonglong2 ya = ldu2(yrow), yb = ldu2(yrow + 4);
    const u64 r2 = bc2(rad);
    u64 A[4] = {ya.x, ya.y, yb.x, yb.y};
    fadd2(A[0], pre[0]); fadd2(A[1], pre[1]);
    fadd2(A[2], pre[2]); fadd2(A[3], pre[3]);
    ffma2(A[0], w32a.x, r2); ffma2(A[1], w32a.y, r2);
    ffma2(A[2], w32b.x, r2); ffma2(A[3], w32b.y, r2);
    unp8(A, o);
    #pragma unroll
    for (int k = 0; k < 8; ++k) o[k] = silu_f(o[k]);
}

__global__ void __launch_bounds__(2 * N_, 2)
egnn_kernel(const float* __restrict__ data,      // [B, N, 3+N]
            const float* __restrict__ emb_w,     // [N, H]
            const float* __restrict__ ein_w, const float* __restrict__ ein_b,
            const float* __restrict__ eout_w, const float* __restrict__ eout_b,
            const float* __restrict__ fc_w,  const float* __restrict__ fc_b,
            const float* __restrict__ e1_w,  const float* __restrict__ e1_b,
            const float* __restrict__ e2_w,  const float* __restrict__ e2_b,
            const float* __restrict__ n1_w,  const float* __restrict__ n1_b,
            const float* __restrict__ n2_w,  const float* __restrict__ n2_b,
            const float* __restrict__ c1_w,  const float* __restrict__ c1_b,
            const float* __restrict__ c2_w,
            float* __restrict__ out)             // [B, NC]
{
    const int b   = blockIdx.x;
    const int tid = threadIdx.x;
    const int i   = tid >> 1;        // node 0..127
    const int e   = tid & 1;         // lane within pair
    const int co  = e * 8;           // owned output-column slice base

    __shared__ __align__(16) float s_h[N_][HS];
    __shared__ __align__(16) float s_y[N_][HS];
    __shared__ __align__(16) float4 s_x4[N_];

    __shared__ __align__(16) float w_e1[NL_ * SZ_E1 + SMEM_PAD], w_e2[NL_ * SZ_E2];
    __shared__ __align__(16) float w_n1[NL_ * SZ_N1], w_n2[NL_ * SZ_N2];
    __shared__ __align__(16) float w_c1[NL_ * SZ_C1], w_c2[NL_ * SZ_C2];
    __shared__ __align__(16) float b_e1[NL_ * 16], b_e2[NL_ * 16];
    __shared__ __align__(16) float b_n1[NL_ * 16], b_n2[NL_ * 16], b_c1[NL_ * 16];
    __shared__ __align__(16) float s_ein[16 * 16], sb_ein[16];
    __shared__ __align__(16) float s_eout[16 * 16], sb_eout[16];
    __shared__ float s_fc[16 * NC_], sb_fc[NC_];
    __shared__ float s_pool[H_];

    const int NT = 2 * N_;
    for (int t = tid; t < NL_ * SZ_E1; t += NT) w_e1[t] = e1_w[t];
    for (int t = tid; t < NL_ * SZ_E2; t += NT) w_e2[t] = e2_w[t];
    for (int t = tid; t < NL_ * SZ_N1; t += NT) w_n1[t] = n1_w[t];
    for (int t = tid; t < NL_ * SZ_N2; t += NT) w_n2[t] = n2_w[t];
    for (int t = tid; t < NL_ * SZ_C1; t += NT) w_c1[t] = c1_w[t];
    for (int t = tid; t < NL_ * SZ_C2; t += NT) w_c2[t] = c2_w[t];
    for (int t = tid; t < NL_ * 16; t += NT) {
        b_e1[t] = e1_b[t]; b_e2[t] = e2_b[t];
        b_n1[t] = n1_b[t]; b_n2[t] = n2_b[t]; b_c1[t] = c1_b[t];
    }
    for (int t = tid; t < 16 * 16; t += NT) { s_ein[t] = ein_w[t]; s_eout[t] = eout_w[t]; }
    if (tid < 16) { sb_ein[tid] = ein_b[tid]; sb_eout[tid] = eout_b[tid]; }
    for (int t = tid; t < 16 * NC_; t += NT) s_fc[t] = fc_w[t];
    if (tid < NC_) sb_fc[tid] = fc_b[tid];

    float xi0, xi1, xi2;
    {
        const float* dptr = data + ((size_t)b * N_ + i) * (3 + N_);
        xi0 = dptr[0]; xi1 = dptr[1]; xi2 = dptr[2];
    }
    __syncthreads();

    // ---- init: h = emb @ ein_w + ein_b ----
    {
        u64 acc[4];
        pbias8(acc, sb_ein + co);
        const float* er = emb_w + i * H_;
        #pragma unroll
        for (int k = 0; k < 16; ++k) pfma8(acc, bc2(er[k]), s_ein + k * 16 + co);
        stu2(&s_h[i][co], acc);
        if (e == 0) s_x4[i] = make_float4(xi0, xi1, xi2, 0.0f);
    }
    __syncthreads();

    // ---- E_GCL layers ----
    #pragma unroll 1
    for (int l = 0; l < NL_; ++l) {
        const float* We1c = w_e1 + l * SZ_E1 + co;
        const float* Be2  = b_e2 + l * 16 + co;
        const float* Bc1  = b_c1 + l * 16 + co;
        const float* E2o = w_e2 + l * SZ_E2 + co * 16       + co;
        const float* E2x = w_e2 + l * SZ_E2 + (8 - co) * 16 + co;
        const float* C1o = w_c1 + l * SZ_C1 + co * 16       + co;
        const float* C1x = w_c1 + l * SZ_C1 + (8 - co) * 16 + co;

        // Phase A: pre = bias + e_attr row + h_i @ rows0-15; y_i -> s_y
        u64 pre[4];
        {
            float hf[16]; load16(hf, &s_h[i][0]);
            pbias8(pre, b_e1 + l * 16 + co);
            pfma8(pre, bc2(1.0f), We1c + 33 * 16);
            u64 yq[4] = {0, 0, 0, 0};
            #pragma unroll
            for (int k = 0; k < 16; ++k) {
                const u64 s2 = bc2(hf[k]);
                pfma8(pre, s2, We1c + k * 16);
                pfma8(yq,  s2, We1c + (16 + k) * 16);
            }
            stu2(&s_y[i][co], yq);
        }
        __syncthreads();

        float accm[8] = {0,0,0,0,0,0,0,0};
        float ax0 = 0.f, ax1 = 0.f, ax2 = 0.f;

        #pragma unroll 1
        for (int it = 0; it < 4; ++it) {       // 4 edges per iteration
            const int d  = 1 + 4 * it;
            const int j0 = (i + d)     & (N_ - 1);
            const int j1 = (i + d + 1) & (N_ - 1);
            const int j2 = (i + d + 2) & (N_ - 1);
            const int j3 = (i + d + 3) & (N_ - 1);

            // e1: a_k = silu(pre + y_jk + rad_k * w32)
            float a0[8], a1[8], a2[8], a3[8];
            {
                ulonglong2 w32a = ldu2(We1c + 32*16), w32b = ldu2(We1c + 32*16 + 4);
                float4 x0 = s_x4[j0], x1 = s_x4[j1], x2 = s_x4[j2], x3 = s_x4[j3];
                float dx, dy, dz;
                dx = xi0-x0.x; dy = xi1-x0.y; dz = xi2-x0.z;
                const float rad0 = fmaf(dx,dx, fmaf(dy,dy, dz*dz));
                dx = xi0-x1.x; dy = xi1-x1.y; dz = xi2-x1.z;
                const float rad1 = fmaf(dx,dx, fmaf(dy,dy, dz*dz));
                dx = xi0-x2.x; dy = xi1-x2.y; dz = xi2-x2.z;
                const float rad2 = fmaf(dx,dx, fmaf(dy,dy, dz*dz));
                dx = xi0-x3.x; dy = xi1-x3.y; dz = xi2-x3.z;
                const float rad3 = fmaf(dx,dx, fmaf(dy,dy, dz*dz));
                e1_edge(a0, &s_y[j0][co], pre, w32a, w32b, rad0);
                e1_edge(a1, &s_y[j1][co], pre, w32a, w32b, rad1);
                e1_edge(a2, &s_y[j2][co], pre, w32a, w32b, rad2);
                e1_edge(a3, &s_y[j3][co], pre, w32a, w32b, rad3);
            }

            // e2: m_k = silu(a_full @ We2 + b); one row-load serves 4 edges
            float m0[8], m1[8], m2[8], m3[8];
            {
                u64 M0[4], M1[4], M2[4], M3[4];
                pbias8(M0, Be2);
                #pragma unroll
                for (int p = 0; p < 4; ++p) { M1[p]=M0[p]; M2[p]=M0[p]; M3[p]=M0[p]; }
                #pragma unroll
                for (int r = 0; r < 8; ++r)
                    pfma8x4(M0, M1, M2, M3,
                            bc2(a0[r]), bc2(a1[r]), bc2(a2[r]), bc2(a3[r]),
                            E2o + r * 16);
                #pragma unroll
                for (int r = 0; r < 8; ++r) {
                    const float s0 = __shfl_xor_sync(FULL, a0[r], 1);
                    const float s1 = __shfl_xor_sync(FULL, a1[r], 1);
                    const float s2 = __shfl_xor_sync(FULL, a2[r], 1);
                    const float s3 = __shfl_xor_sync(FULL, a3[r], 1);
                    pfma8x4(M0, M1, M2, M3, bc2(s0), bc2(s1), bc2(s2), bc2(s3),
                            E2x + r * 16);
                }
                unp8(M0, m0); unp8(M1, m1); unp8(M2, m2); unp8(M3, m3);
            }
            #pragma unroll
            for (int o = 0; o < 8; ++o) {
                m0[o] = silu_f(m0[o]); m1[o] = silu_f(m1[o]);
                m2[o] = silu_f(m2[o]); m3[o] = silu_f(m3[o]);
                accm[o] += (m0[o] + m1[o]) + (m2[o] + m3[o]);
            }

            // coord_mlp: t_k = silu(m_full @ Wc1 + b) . Wc2 (reuse a regs)
            {
                u64 T0[4], T1[4], T2[4], T3[4];
                pbias8(T0, Bc1);
                #pragma unroll
                for (int p = 0; p < 4; ++p) { T1[p]=T0[p]; T2[p]=T0[p]; T3[p]=T0[p]; }
                #pragma unroll
                for (int r = 0; r < 8; ++r)
                    pfma8x4(T0, T1, T2, T3,
                            bc2(m0[r]), bc2(m1[r]), bc2(m2[r]), bc2(m3[r]),
                            C1o + r * 16);
                #pragma unroll
                for (int r = 0; r < 8; ++r) {
                    const float s0 = __shfl_xor_sync(FULL, m0[r], 1);
                    const float s1 = __shfl_xor_sync(FULL, m1[r], 1);
                    const float s2 = __shfl_xor_sync(FULL, m2[r], 1);
                    const float s3 = __shfl_xor_sync(FULL, m3[r], 1);
                    pfma8x4(T0, T1, T2, T3, bc2(s0), bc2(s1), bc2(s2), bc2(s3),
                            C1x + r * 16);
                }
                unp8(T0, a0); unp8(T1, a1); unp8(T2, a2); unp8(T3, a3);
            }
            float t0, t1, t2, t3;
            {
                float4 w0 = ld4(w_c2 + l * SZ_C2 + co);
                float4 w1 = ld4(w_c2 + l * SZ_C2 + co + 4);
                t0 = silu_f(a0[0]) * w0.x;
                t0 = fmaf(silu_f(a0[1]), w0.y, t0);
                t0 = fmaf(silu_f(a0[2]), w0.z, t0);
                t0 = fmaf(silu_f(a0[3]), w0.w, t0);
                t0 = fmaf(silu_f(a0[4]), w1.x, t0);
                t0 = fmaf(silu_f(a0[5]), w1.y, t0);
                t0 = fmaf(silu_f(a0[6]), w1.z, t0);
                t0 = fmaf(silu_f(a0[7]), w1.w, t0);
                t1 = silu_f(a1[0]) * w0.x;
                t1 = fmaf(silu_f(a1[1]), w0.y, t1);
                t1 = fmaf(silu_f(a1[2]), w0.z, t1);
                t1 = fmaf(silu_f(a1[3]), w0.w, t1);
                t1 = fmaf(silu_f(a1[4]), w1.x, t1);
                t1 = fmaf(silu_f(a1[5]), w1.y, t1);
                t1 = fmaf(silu_f(a1[6]), w1.z, t1);
                t1 = fmaf(silu_f(a1[7]), w1.w, t1);
                t2 = silu_f(a2[0]) * w0.x;
                t2 = fmaf(silu_f(a2[1]), w0.y, t2);
                t2 = fmaf(silu_f(a2[2]), w0.z, t2);
                t2 = fmaf(silu_f(a2[3]), w0.w, t2);
                t2 = fmaf(silu_f(a2[4]), w1.x, t2);
                t2 = fmaf(silu_f(a2[5]), w1.y, t2);
                t2 = fmaf(silu_f(a2[6]), w1.z, t2);
                t2 = fmaf(silu_f(a2[7]), w1.w, t2);
                t3 = silu_f(a3[0]) * w0.x;
                t3 = fmaf(silu_f(a3[1]), w0.y, t3);
                t3 = fmaf(silu_f(a3[2]), w0.z, t3);
                t3 = fmaf(silu_f(a3[3]), w0.w, t3);
                t3 = fmaf(silu_f(a3[4]), w1.x, t3);
                t3 = fmaf(silu_f(a3[5]), w1.y, t3);
                t3 = fmaf(silu_f(a3[6]), w1.z, t3);
                t3 = fmaf(silu_f(a3[7]), w1.w, t3);
            }
            t0 += __shfl_xor_sync(FULL, t0, 1);
            t1 += __shfl_xor_sync(FULL, t1, 1);
            t2 += __shfl_xor_sync(FULL, t2, 1);
            t3 += __shfl_xor_sync(FULL, t3, 1);

            // apply coord contributions (recompute diffs from s_x4)
            {
                float4 x0 = s_x4[j0], x1 = s_x4[j1], x2 = s_x4[j2], x3 = s_x4[j3];
                ax0 = fmaf(xi0-x0.x, t0, fmaf(xi0-x1.x, t1,
                      fmaf(xi0-x2.x, t2, fmaf(xi0-x3.x, t3, ax0))));
                ax1 = fmaf(xi1-x0.y, t0, fmaf(xi1-x1.y, t1,
                      fmaf(xi1-x2.y, t2, fmaf(xi1-x3.y, t3, ax1))));
                ax2 = fmaf(xi2-x0.z, t0, fmaf(xi2-x1.z, t1,
                      fmaf(xi2-x2.z, t2, fmaf(xi2-x3.z, t3, ax2))));
            }
        }

        xi0 = fmaf(ax0, 0.0625f, xi0);   // cnt == 16
        xi1 = fmaf(ax1, 0.0625f, xi1);
        xi2 = fmaf(ax2, 0.0625f, xi2);

        __syncthreads();   // all Phase-B reads of s_y / s_x done block-wide

        // Phase C: node_mlp (pair-split 8/8, packed)
        {
            const float* Wn1c = w_n1 + l * SZ_N1 + co;
            const float* N1o = w_n1 + l * SZ_N1 + (16 + co) * 16     + co;
            const float* N1x = w_n1 + l * SZ_N1 + (16 + 8 - co) * 16 + co;
            const float* N2o = w_n2 + l * SZ_N2 + co * 16       + co;
            const float* N2x = w_n2 + l * SZ_N2 + (8 - co) * 16 + co;

            float hf[16]; load16(hf, &s_h[i][0]);
            float na[8];
            {
                u64 NA[4];
                pbias8(NA, b_n1 + l * 16 + co);
                #pragma unroll
                for (int k = 0; k < 16; ++k) pfma8(NA, bc2(hf[k]), Wn1c + k * 16);
                #pragma unroll
                for (int r = 0; r < 8; ++r) pfma8(NA, bc2(accm[r]), N1o + r * 16);
                #pragma unroll
                for (int r = 0; r < 8; ++r)
                    pfma8(NA, bc2(__shfl_xor_sync(FULL, accm[r], 1)), N1x + r * 16);
                unp8(NA, na);
            }
            #pragma unroll
            for (int o = 0; o < 8; ++o) na[o] = silu_f(na[o]);

            float hb[8];
            {
                u64 HB[4];
                pbias8(HB, b_n2 + l * 16 + co);
                #pragma unroll
                for (int r = 0; r < 8; ++r) pfma8(HB, bc2(na[r]), N2o + r * 16);
                #pragma unroll
                for (int r = 0; r < 8; ++r)
                    pfma8(HB, bc2(__shfl_xor_sync(FULL, na[r], 1)), N2x + r * 16);
                unp8(HB, hb);
            }
            {
                float4 r0 = ld4(&s_h[i][co]), r1 = ld4(&s_h[i][co + 4]);
                hb[0] += r0.x; hb[1] += r0.y; hb[2] += r0.z; hb[3] += r0.w;
                hb[4] += r1.x; hb[5] += r1.y; hb[6] += r1.z; hb[7] += r1.w;
            }
            __syncwarp();
            st8(&s_h[i][co], hb);
            if (e == 0) s_x4[i] = make_float4(xi0, xi1, xi2, 0.0f);
        }
        __syncwarp();
    }

    // ---- embedding_out + pooling ----
    {
        float hf[16]; load16(hf, &s_h[i][0]);
        u64 HO[4];
        pbias8(HO, sb_eout + co);
        #pragma unroll
        for (int k = 0; k < 16; ++k) pfma8(HO, bc2(hf[k]), s_eout + k * 16 + co);
        __syncthreads();
        stu2(&s_h[i][co], HO);
    }
    __syncthreads();

    if (tid < H_) {
        float s = 0.0f;
        for (int j = 0; j < N_; ++j) s += s_h[j][tid];
        s_pool[tid] = s * (1.0f / (float)N_);
    }
    __syncthreads();

    if (tid == 0) {
        float logit[NC_];
        float mx = -1e30f;
        #pragma unroll
        for (int c = 0; c < NC_; ++c) {
            float s = sb_fc[c];
            #pragma unroll
            for (int k = 0; k < H_; ++k) s = fmaf(s_pool[k], s_fc[k * NC_ + c], s);
            logit[c] = s;
            mx = fmaxf(mx, s);
        }
        float den = 0.0f;
        float ev[NC_];
        #pragma unroll
        for (int c = 0; c < NC_; ++c) { ev[c] = expf(logit[c] - mx); den += ev[c]; }
        const float inv = 1.0f / den;
        #pragma unroll
        for (int c = 0; c < NC_; ++c) out[b * NC_ + c] = ev[c] * inv;
    }
}

extern "C" void kernel_launch(void* const* d_in, const int* in_sizes, int n_in,
                              void* d_out, int out_size)
{
    const float* data   = (const float*)d_in[0];
    const float* emb_w  = (const float*)d_in[3];
    const float* ein_w  = (const float*)d_in[4];
    const float* ein_b  = (const float*)d_in[5];
    const float* eout_w = (const float*)d_in[6];
    const float* eout_b = (const float*)d_in[7];
    const float* fc_w   = (const float*)d_in[8];
    const float* fc_b   = (const float*)d_in[9];
    const float* e1_w   = (const float*)d_in[10];
    const float* e1_b   = (const float*)d_in[11];
    const float* e2_w   = (const float*)d_in[12];
    const float* e2_b   = (const float*)d_in[13];
    const float* n1_w   = (const float*)d_in[14];
    const float* n1_b   = (const float*)d_in[15];
    const float* n2_w   = (const float*)d_in[16];
    const float* n2_b   = (const float*)d_in[17];
    const float* c1_w   = (const float*)d_in[18];
    const float* c1_b   = (const float*)d_in[19];
    const float* c2_w   = (const float*)d_in[20];
    float* out = (float*)d_out;

    egnn_kernel<<<B_, 2 * N_>>>(data, emb_w, ein_w, ein_b, eout_w, eout_b,
                                fc_w, fc_b, e1_w, e1_b, e2_w, e2_b,
                                n1_w, n1_b, n2_w, n2_b, c1_w, c1_b, c2_w, out);
}